// round 7
// baseline (speedup 1.0000x reference)
#include <cuda_runtime.h>
#include <cstdint>

// ---------------- problem constants ----------------
constexpr int NTOK  = 197;
constexpr int DIMC  = 768;
constexpr int NH    = 12;
constexpr int HDIM  = 64;
constexpr int NB    = 128;
constexpr int MROWS = NB * NTOK;    // 25216
constexpr int NBH   = NB * NH;      // 1536

// ---------------- scratch (device globals) ----------------
__device__ float g_q[(size_t)NBH * NTOK * HDIM];
__device__ float g_k[(size_t)NBH * NTOK * HDIM];
__device__ float g_v[(size_t)NBH * NTOK * HDIM];
__device__ float g_o[(size_t)MROWS * DIMC];
__device__ float g_rpb[NH * NTOK * NTOK];

// ---------------- helpers ----------------
__device__ __forceinline__ float f2tf32(float x) {
    unsigned u;
    asm("cvt.rna.tf32.f32 %0, %1;" : "=r"(u) : "f"(x));
    return __uint_as_float(u);
}

__device__ __forceinline__ void mma_tf32(float c[4], const float a[4], const float b[2]) {
    asm volatile(
        "mma.sync.aligned.m16n8k8.row.col.f32.tf32.tf32.f32 "
        "{%0,%1,%2,%3}, {%4,%5,%6,%7}, {%8,%9}, {%0,%1,%2,%3};"
        : "+f"(c[0]), "+f"(c[1]), "+f"(c[2]), "+f"(c[3])
        : "r"(__float_as_uint(a[0])), "r"(__float_as_uint(a[1])),
          "r"(__float_as_uint(a[2])), "r"(__float_as_uint(a[3])),
          "r"(__float_as_uint(b[0])), "r"(__float_as_uint(b[1])));
}

__device__ __forceinline__ void ldsm_x4(uint32_t addr, float d[4]) {
    uint32_t r0, r1, r2, r3;
    asm volatile("ldmatrix.sync.aligned.m8n8.x4.shared.b16 {%0,%1,%2,%3}, [%4];"
                 : "=r"(r0), "=r"(r1), "=r"(r2), "=r"(r3) : "r"(addr));
    d[0] = __uint_as_float(r0); d[1] = __uint_as_float(r1);
    d[2] = __uint_as_float(r2); d[3] = __uint_as_float(r3);
}

__device__ __forceinline__ uint32_t smem_u32(const void* p) {
    return (uint32_t)__cvta_generic_to_shared(p);
}

// ---------------- rpb gather expansion ----------------
__global__ void rpb_expand_k(const int* __restrict__ rel_idx,
                             const float* __restrict__ table)
{
    int ij = blockIdx.x * 256 + threadIdx.x;
    if (ij >= NTOK * NTOK) return;
    int rel = rel_idx[ij];
    #pragma unroll
    for (int h = 0; h < NH; h++)
        g_rpb[h * NTOK * NTOK + ij] = table[rel * NH + h];
}

// ---------------- TF32 GEMM (ldmatrix, 128x256 block, 64x64 warp tile) -------
// MODE 0: QKV  [25216,2304] = x @ qkv_w^T (+bias, scale, scatter q/k/v)
// MODE 3: proj [25216,768]  = g_o @ proj_w^T (+bias)
// 8 warps in 2(M)x4(N); double-buffered dynamic smem, stride 20 (LDSM phase-free).
constexpr int GBM = 128, GBN = 256, GBK = 16, GLD = 20;
constexpr int GEMM_SMEM = 2 * (GBM + GBN) * GLD * 4;   // 61440 B

template<int MODE>
__global__ void __launch_bounds__(256, 1) gemm_tc(const float* __restrict__ A_,
                                                  const float* __restrict__ B_,
                                                  const float* __restrict__ P1,
                                                  const float* __restrict__ P2,
                                                  float* __restrict__ C_)
{
    constexpr int Kdim = DIMC;
    constexpr int NKT  = Kdim / GBK;               // 48

    const float* A  = (MODE == 3) ? (const float*)g_o : A_;
    const float* Bm = B_;

    const int m0  = blockIdx.y * GBM;
    const int n0  = blockIdx.x * GBN;
    const int tid = threadIdx.x;
    const int w    = tid >> 5, lane = tid & 31;
    const int gid  = lane >> 2, tig = lane & 3;
    const int wm   = (w & 1) * 64;
    const int wn   = (w >> 1) * 64;

    extern __shared__ float smg[];
    float* As = smg;                         // [2][GBM*GLD]
    float* Bs = smg + 2 * GBM * GLD;         // [2][GBN*GLD]

    // staging: 4 lanes per row, coalesced 64B segments
    const int sr = tid >> 2;            // 0..63
    const int sc = (tid & 3) * 4;

    const float* pa0 = &A [(size_t)(m0 + sr     ) * Kdim + sc];
    const float* pa1 = &A [(size_t)(m0 + sr + 64) * Kdim + sc];
    const float* pb0 = &Bm[(size_t)(n0 + sr      ) * Kdim + sc];
    const float* pb1 = &Bm[(size_t)(n0 + sr +  64) * Kdim + sc];
    const float* pb2 = &Bm[(size_t)(n0 + sr + 128) * Kdim + sc];
    const float* pb3 = &Bm[(size_t)(n0 + sr + 192) * Kdim + sc];

    float4 va0, va1, vb0, vb1, vb2, vb3;
    float acc[4][8][4] = {};

    // LDSM lane geometry
    const int lt   = lane >> 3;
    const int li   = lane & 7;
    const int a_row = wm + (lt & 1) * 8 + li;        // + mt*16
    const int a_col = (lt >> 1) * 4;                 // + kc*8
    const int b_row = wn + (lt >> 1) * 8 + li;       // + p*16
    const int b_col = (lt & 1) * 4;                  // + kc*8

    auto LDG = [&](int kt) {
        va0 = *(const float4*)(pa0 + kt);
        va1 = *(const float4*)(pa1 + kt);
        vb0 = *(const float4*)(pb0 + kt);
        vb1 = *(const float4*)(pb1 + kt);
        vb2 = *(const float4*)(pb2 + kt);
        vb3 = *(const float4*)(pb3 + kt);
    };
    auto STS = [&](int buf) {
        float* ab = As + buf * GBM * GLD;
        float* bb = Bs + buf * GBN * GLD;
        float4 t;
        t = make_float4(f2tf32(va0.x), f2tf32(va0.y), f2tf32(va0.z), f2tf32(va0.w));
        *(float4*)&ab[(sr      ) * GLD + sc] = t;
        t = make_float4(f2tf32(va1.x), f2tf32(va1.y), f2tf32(va1.z), f2tf32(va1.w));
        *(float4*)&ab[(sr +  64) * GLD + sc] = t;
        t = make_float4(f2tf32(vb0.x), f2tf32(vb0.y), f2tf32(vb0.z), f2tf32(vb0.w));
        *(float4*)&bb[(sr      ) * GLD + sc] = t;
        t = make_float4(f2tf32(vb1.x), f2tf32(vb1.y), f2tf32(vb1.z), f2tf32(vb1.w));
        *(float4*)&bb[(sr +  64) * GLD + sc] = t;
        t = make_float4(f2tf32(vb2.x), f2tf32(vb2.y), f2tf32(vb2.z), f2tf32(vb2.w));
        *(float4*)&bb[(sr + 128) * GLD + sc] = t;
        t = make_float4(f2tf32(vb3.x), f2tf32(vb3.y), f2tf32(vb3.z), f2tf32(vb3.w));
        *(float4*)&bb[(sr + 192) * GLD + sc] = t;
    };
    auto MMA_ALL = [&](int buf) {
        const float* ab = As + buf * GBM * GLD;
        const float* bb = Bs + buf * GBN * GLD;
        #pragma unroll
        for (int kc = 0; kc < 2; kc++) {
            float af[4][4], bf[8][2];
            #pragma unroll
            for (int mt = 0; mt < 4; mt++) {
                uint32_t ad = smem_u32(&ab[(a_row + mt * 16) * GLD + a_col + kc * 8]);
                ldsm_x4(ad, af[mt]);
            }
            #pragma unroll
            for (int p = 0; p < 4; p++) {
                float t4[4];
                uint32_t ad = smem_u32(&bb[(b_row + p * 16) * GLD + b_col + kc * 8]);
                ldsm_x4(ad, t4);
                bf[p*2  ][0] = t4[0]; bf[p*2  ][1] = t4[1];
                bf[p*2+1][0] = t4[2]; bf[p*2+1][1] = t4[3];
            }
            #pragma unroll
            for (int mt = 0; mt < 4; mt++)
                #pragma unroll
                for (int nt = 0; nt < 8; nt++)
                    mma_tf32(acc[mt][nt], af[mt], bf[nt]);
        }
    };

    LDG(0);
    STS(0);
    __syncthreads();
    int cur = 0;
    for (int it = 1; it < NKT; it++) {
        LDG(it * GBK);
        MMA_ALL(cur);
        STS(cur ^ 1);
        __syncthreads();
        cur ^= 1;
    }
    MMA_ALL(cur);

    // ---- fused epilogues ----
    #pragma unroll
    for (int mt = 0; mt < 4; mt++) {
        #pragma unroll
        for (int nt = 0; nt < 8; nt++) {
            #pragma unroll
            for (int e = 0; e < 4; e++) {
                int gm = m0 + wm + mt * 16 + gid + ((e >> 1) ? 8 : 0);
                int gn = n0 + wn + nt * 8 + tig * 2 + (e & 1);
                float v = acc[mt][nt][e];
                if (MODE == 0) {
                    int b = gm / NTOK, n = gm % NTOK;
                    int s = gn / DIMC, r = gn % DIMC;
                    int h = r / HDIM,  d = r % HDIM;
                    size_t o = ((size_t)(b * NH + h) * NTOK + n) * HDIM + d;
                    if (s == 0)      g_q[o] = (v + P1[r]) * 0.125f;
                    else if (s == 1) g_k[o] = v;
                    else             g_v[o] = v + P2[r];
                } else {
                    C_[(size_t)gm * DIMC + gn] = v + P1[gn];
                }
            }
        }
    }
}

// ---------------- fused attention: S = QK^T + rpb -> softmax -> P V ----------
constexpr int NP        = 208;
constexpr int KS_STRIDE = 68;
constexpr int VT_STRIDE = 212;
constexpr int ATT_SMEM  = (NP * KS_STRIDE + HDIM * VT_STRIDE) * 4;

__global__ void __launch_bounds__(256, 1) attn_fused_k()
{
    const int z = blockIdx.x;
    const int h = z % NH;
    const int b = z / NH;
    const float* q   = g_q + (size_t)z * NTOK * HDIM;
    const float* kk  = g_k + (size_t)z * NTOK * HDIM;
    const float* vv  = g_v + (size_t)z * NTOK * HDIM;
    const float* rpb = g_rpb + (size_t)h * NTOK * NTOK;

    extern __shared__ float sm[];
    float* ks = sm;
    float* vT = sm + NP * KS_STRIDE;

    const int tid = threadIdx.x;

    for (int idx = tid; idx < NP * 16; idx += 256) {
        int tok = idx >> 4, d4 = (idx & 15) * 4;
        float4 val = make_float4(0.f, 0.f, 0.f, 0.f);
        if (tok < NTOK) val = *(const float4*)&kk[tok * HDIM + d4];
        ks[tok * KS_STRIDE + d4 + 0] = f2tf32(val.x);
        ks[tok * KS_STRIDE + d4 + 1] = f2tf32(val.y);
        ks[tok * KS_STRIDE + d4 + 2] = f2tf32(val.z);
        ks[tok * KS_STRIDE + d4 + 3] = f2tf32(val.w);
    }
    for (int idx = tid; idx < NP * 16; idx += 256) {
        int tok = idx >> 4, d4 = (idx & 15) * 4;
        float4 val = make_float4(0.f, 0.f, 0.f, 0.f);
        if (tok < NTOK) val = *(const float4*)&vv[tok * HDIM + d4];
        vT[(d4 + 0) * VT_STRIDE + tok] = f2tf32(val.x);
        vT[(d4 + 1) * VT_STRIDE + tok] = f2tf32(val.y);
        vT[(d4 + 2) * VT_STRIDE + tok] = f2tf32(val.z);
        vT[(d4 + 3) * VT_STRIDE + tok] = f2tf32(val.w);
    }
    __syncthreads();

    const int w = tid >> 5, lane = tid & 31, gid = lane >> 2, tig = lane & 3;

    for (int r = 0; r < 2; r++) {
        const int t = w + 8 * r;
        if (t >= 13) break;
        const int m0 = t * 16;
        const int mA = m0 + gid;
        const int mB = m0 + gid + 8;

        float aq[8][4];
        #pragma unroll
        for (int kt = 0; kt < 8; kt++) {
            int c0 = kt * 8 + tig, c1 = c0 + 4;
            aq[kt][0] = (mA < NTOK) ? f2tf32(q[mA * HDIM + c0]) : 0.f;
            aq[kt][1] = (mB < NTOK) ? f2tf32(q[mB * HDIM + c0]) : 0.f;
            aq[kt][2] = (mA < NTOK) ? f2tf32(q[mA * HDIM + c1]) : 0.f;
            aq[kt][3] = (mB < NTOK) ? f2tf32(q[mB * HDIM + c1]) : 0.f;
        }

        float acc[26][4];
        #pragma unroll
        for (int nt = 0; nt < 26; nt++)
            acc[nt][0] = acc[nt][1] = acc[nt][2] = acc[nt][3] = 0.f;
        #pragma unroll
        for (int nt = 0; nt < 26; nt++) {
            const int n = nt * 8 + gid;
            #pragma unroll
            for (int kt = 0; kt < 8; kt++) {
                float bk[2];
                bk[0] = ks[n * KS_STRIDE + kt * 8 + tig];
                bk[1] = ks[n * KS_STRIDE + kt * 8 + tig + 4];
                mma_tf32(acc[nt], aq[kt], bk);
            }
        }

        const float* rA = rpb + (size_t)min(mA, NTOK - 1) * NTOK;
        const float* rB = rpb + (size_t)min(mB, NTOK - 1) * NTOK;
        float mx0 = -1e30f, mx1 = -1e30f;
        #pragma unroll
        for (int nt = 0; nt < 26; nt++) {
            int c0 = nt * 8 + tig * 2, c1 = c0 + 1;
            acc[nt][0] = (c0 < NTOK) ? acc[nt][0] + rA[c0] : -1e30f;
            acc[nt][1] = (c1 < NTOK) ? acc[nt][1] + rA[c1] : -1e30f;
            acc[nt][2] = (c0 < NTOK) ? acc[nt][2] + rB[c0] : -1e30f;
            acc[nt][3] = (c1 < NTOK) ? acc[nt][3] + rB[c1] : -1e30f;
            mx0 = fmaxf(mx0, fmaxf(acc[nt][0], acc[nt][1]));
            mx1 = fmaxf(mx1, fmaxf(acc[nt][2], acc[nt][3]));
        }
        #pragma unroll
        for (int o = 1; o <= 2; o <<= 1) {
            mx0 = fmaxf(mx0, __shfl_xor_sync(~0u, mx0, o));
            mx1 = fmaxf(mx1, __shfl_xor_sync(~0u, mx1, o));
        }
        float s0 = 0.f, s1 = 0.f;
        #pragma unroll
        for (int nt = 0; nt < 26; nt++) {
            acc[nt][0] = __expf(acc[nt][0] - mx0);
            acc[nt][1] = __expf(acc[nt][1] - mx0);
            acc[nt][2] = __expf(acc[nt][2] - mx1);
            acc[nt][3] = __expf(acc[nt][3] - mx1);
            s0 += acc[nt][0] + acc[nt][1];
            s1 += acc[nt][2] + acc[nt][3];
        }
        #pragma unroll
        for (int o = 1; o <= 2; o <<= 1) {
            s0 += __shfl_xor_sync(~0u, s0, o);
            s1 += __shfl_xor_sync(~0u, s1, o);
        }
        const float i0 = 1.f / s0, i1 = 1.f / s1;
        #pragma unroll
        for (int nt = 0; nt < 26; nt++) {
            acc[nt][0] *= i0; acc[nt][1] *= i0;
            acc[nt][2] *= i1; acc[nt][3] *= i1;
        }

        float acc2[8][4];
        #pragma unroll
        for (int nt = 0; nt < 8; nt++)
            acc2[nt][0] = acc2[nt][1] = acc2[nt][2] = acc2[nt][3] = 0.f;

        const int src0 = (lane & ~3) | (tig >> 1);
        const int src1 = src0 + 2;
        const bool odd = tig & 1;
        #pragma unroll
        for (int kt = 0; kt < 26; kt++) {
            float v00 = __shfl_sync(~0u, acc[kt][0], src0);
            float v01 = __shfl_sync(~0u, acc[kt][1], src0);
            float v02 = __shfl_sync(~0u, acc[kt][2], src0);
            float v03 = __shfl_sync(~0u, acc[kt][3], src0);
            float w00 = __shfl_sync(~0u, acc[kt][0], src1);
            float w01 = __shfl_sync(~0u, acc[kt][1], src1);
            float w02 = __shfl_sync(~0u, acc[kt][2], src1);
            float w03 = __shfl_sync(~0u, acc[kt][3], src1);
            float aP[4];
            aP[0] = f2tf32(odd ? v01 : v00);
            aP[1] = f2tf32(odd ? v03 : v02);
            aP[2] = f2tf32(odd ? w01 : w00);
            aP[3] = f2tf32(odd ? w03 : w02);
            #pragma unroll
            for (int nt = 0; nt < 8; nt++) {
                float bv[2];
                bv[0] = vT[(nt * 8 + gid) * VT_STRIDE + kt * 8 + tig];
                bv[1] = vT[(nt * 8 + gid) * VT_STRIDE + kt * 8 + tig + 4];
                mma_tf32(acc2[nt], aP, bv);
            }
        }

        #pragma unroll
        for (int nt = 0; nt < 8; nt++) {
            int d0 = nt * 8 + tig * 2;
            if (mA < NTOK) {
                float* o = &g_o[((size_t)(b * NTOK + mA)) * DIMC + h * HDIM + d0];
                o[0] = acc2[nt][0]; o[1] = acc2[nt][1];
            }
            if (mB < NTOK) {
                float* o = &g_o[((size_t)(b * NTOK + mB)) * DIMC + h * HDIM + d0];
                o[0] = acc2[nt][2]; o[1] = acc2[nt][3];
            }
        }
    }
}

// ---------------- launch ----------------
extern "C" void kernel_launch(void* const* d_in, const int* in_sizes, int n_in,
                              void* d_out, int out_size)
{
    const float* x = nullptr; const float* qkv_w = nullptr;
    const float* proj_w = nullptr; const float* rpb_table = nullptr;
    const int*   rel_idx = nullptr;
    const float* bias768[3] = {nullptr, nullptr, nullptr};
    int nbias = 0;
    for (int i = 0; i < n_in; i++) {
        switch (in_sizes[i]) {
            case MROWS * DIMC:    x         = (const float*)d_in[i]; break;
            case 3 * DIMC * DIMC: qkv_w     = (const float*)d_in[i]; break;
            case DIMC * DIMC:     proj_w    = (const float*)d_in[i]; break;
            case NTOK * NTOK:     rel_idx   = (const int*)d_in[i];   break;
            case 732 * NH:        rpb_table = (const float*)d_in[i]; break;
            case DIMC:            if (nbias < 3) bias768[nbias++] = (const float*)d_in[i]; break;
            default: break;
        }
    }
    const float* q_bias = bias768[0];
    const float* v_bias = bias768[1];
    const float* proj_b = bias768[2];
    float* out = (float*)d_out;

    cudaFuncSetAttribute(attn_fused_k, cudaFuncAttributeMaxDynamicSharedMemorySize, ATT_SMEM);
    cudaFuncSetAttribute(gemm_tc<0>, cudaFuncAttributeMaxDynamicSharedMemorySize, GEMM_SMEM);
    cudaFuncSetAttribute(gemm_tc<3>, cudaFuncAttributeMaxDynamicSharedMemorySize, GEMM_SMEM);

    rpb_expand_k<<<(NTOK * NTOK + 255) / 256, 256>>>(rel_idx, rpb_table);

    // 1) QKV projection: grid (2304/256, 25216/128)
    gemm_tc<0><<<dim3(9, 197), 256, GEMM_SMEM>>>(x, qkv_w, q_bias, v_bias, nullptr);

    // 2) fused attention
    attn_fused_k<<<NBH, 256, ATT_SMEM>>>();

    // 3) final projection + bias: grid (768/256, 197)
    gemm_tc<3><<<dim3(3, 197), 256, GEMM_SMEM>>>(nullptr, proj_w, proj_b, nullptr, out);
}

// round 8
// speedup vs baseline: 1.0827x; 1.0827x over previous
#include <cuda_runtime.h>
#include <cstdint>

// ---------------- problem constants ----------------
constexpr int NTOK  = 197;
constexpr int DIMC  = 768;
constexpr int NH    = 12;
constexpr int HDIM  = 64;
constexpr int NB    = 128;
constexpr int MROWS = NB * NTOK;    // 25216
constexpr int NBH   = NB * NH;      // 1536

// ---------------- scratch (device globals) ----------------
__device__ float g_q[(size_t)NBH * NTOK * HDIM];
__device__ float g_k[(size_t)NBH * NTOK * HDIM];
__device__ float g_v[(size_t)NBH * NTOK * HDIM];
__device__ float g_o[(size_t)MROWS * DIMC];
__device__ float g_rpb[NH * NTOK * NTOK];

// ---------------- helpers ----------------
__device__ __forceinline__ float f2tf32(float x) {
    unsigned u;
    asm("cvt.rna.tf32.f32 %0, %1;" : "=r"(u) : "f"(x));
    return __uint_as_float(u);
}

__device__ __forceinline__ void mma_tf32(float c[4], const float a[4], const float b[2]) {
    asm volatile(
        "mma.sync.aligned.m16n8k8.row.col.f32.tf32.tf32.f32 "
        "{%0,%1,%2,%3}, {%4,%5,%6,%7}, {%8,%9}, {%0,%1,%2,%3};"
        : "+f"(c[0]), "+f"(c[1]), "+f"(c[2]), "+f"(c[3])
        : "r"(__float_as_uint(a[0])), "r"(__float_as_uint(a[1])),
          "r"(__float_as_uint(a[2])), "r"(__float_as_uint(a[3])),
          "r"(__float_as_uint(b[0])), "r"(__float_as_uint(b[1])));
}

__device__ __forceinline__ void ldsm_x4(uint32_t addr, float d[4]) {
    uint32_t r0, r1, r2, r3;
    asm volatile("ldmatrix.sync.aligned.m8n8.x4.shared.b16 {%0,%1,%2,%3}, [%4];"
                 : "=r"(r0), "=r"(r1), "=r"(r2), "=r"(r3) : "r"(addr));
    d[0] = __uint_as_float(r0); d[1] = __uint_as_float(r1);
    d[2] = __uint_as_float(r2); d[3] = __uint_as_float(r3);
}

__device__ __forceinline__ uint32_t smem_u32(const void* p) {
    return (uint32_t)__cvta_generic_to_shared(p);
}

// ---------------- rpb gather expansion ----------------
__global__ void rpb_expand_k(const int* __restrict__ rel_idx,
                             const float* __restrict__ table)
{
    int ij = blockIdx.x * 256 + threadIdx.x;
    if (ij >= NTOK * NTOK) return;
    int rel = rel_idx[ij];
    #pragma unroll
    for (int h = 0; h < NH; h++)
        g_rpb[h * NTOK * NTOK + ij] = table[rel * NH + h];
}

// ---------------- TF32 GEMM: 128x128 block, 4 warps of 64x64, 2 CTAs/SM ------
// MODE 0: QKV  [25216,2304] = x @ qkv_w^T (+bias, scale, scatter q/k/v)
// MODE 3: proj [25216,768]  = g_o @ proj_w^T (+bias)
constexpr int GBM = 128, GBN = 128, GBK = 16, GLD = 20;
constexpr int GEMM_SMEM = 2 * (GBM + GBN) * GLD * 4;   // 40960 B

template<int MODE>
__global__ void __launch_bounds__(128, 2) gemm_tc(const float* __restrict__ A_,
                                                  const float* __restrict__ B_,
                                                  const float* __restrict__ P1,
                                                  const float* __restrict__ P2,
                                                  float* __restrict__ C_)
{
    constexpr int Kdim = DIMC;
    constexpr int NKT  = Kdim / GBK;               // 48

    const float* A  = (MODE == 3) ? (const float*)g_o : A_;
    const float* Bm = B_;

    const int m0  = blockIdx.y * GBM;
    const int n0  = blockIdx.x * GBN;
    const int tid = threadIdx.x;
    const int w    = tid >> 5, lane = tid & 31;
    const int gid  = lane >> 2, tig = lane & 3;
    const int wm   = (w & 1) * 64;
    const int wn   = (w >> 1) * 64;

    extern __shared__ float smg[];
    float* As = smg;                         // [2][GBM*GLD]
    float* Bs = smg + 2 * GBM * GLD;         // [2][GBN*GLD]

    // staging: 128 threads, 4 lanes/row, 4 row-passes per tile (coalesced 64B)
    const int sr = tid >> 2;            // 0..31
    const int sc = (tid & 3) * 4;

    const float* pa = &A [(size_t)(m0 + sr) * Kdim + sc];
    const float* pb = &Bm[(size_t)(n0 + sr) * Kdim + sc];

    float4 va[4], vb[4];
    float acc[4][8][4] = {};

    // LDSM lane geometry
    const int lt   = lane >> 3;
    const int li   = lane & 7;
    const int a_row = wm + (lt & 1) * 8 + li;        // + mt*16
    const int a_col = (lt >> 1) * 4;                 // + kc*8
    const int b_row = wn + (lt >> 1) * 8 + li;       // + p*16
    const int b_col = (lt & 1) * 4;                  // + kc*8

    auto LDG = [&](int kt) {
        #pragma unroll
        for (int r = 0; r < 4; r++) {
            va[r] = *(const float4*)(pa + (size_t)(r * 32) * Kdim + kt);
            vb[r] = *(const float4*)(pb + (size_t)(r * 32) * Kdim + kt);
        }
    };
    auto STS = [&](int buf) {
        float* ab = As + buf * GBM * GLD;
        float* bb = Bs + buf * GBN * GLD;
        #pragma unroll
        for (int r = 0; r < 4; r++) {
            float4 t;
            t = make_float4(f2tf32(va[r].x), f2tf32(va[r].y), f2tf32(va[r].z), f2tf32(va[r].w));
            *(float4*)&ab[(sr + r * 32) * GLD + sc] = t;
            t = make_float4(f2tf32(vb[r].x), f2tf32(vb[r].y), f2tf32(vb[r].z), f2tf32(vb[r].w));
            *(float4*)&bb[(sr + r * 32) * GLD + sc] = t;
        }
    };
    auto MMA_ALL = [&](int buf) {
        const float* ab = As + buf * GBM * GLD;
        const float* bb = Bs + buf * GBN * GLD;
        #pragma unroll
        for (int kc = 0; kc < 2; kc++) {
            float af[4][4], bf[8][2];
            #pragma unroll
            for (int mt = 0; mt < 4; mt++) {
                uint32_t ad = smem_u32(&ab[(a_row + mt * 16) * GLD + a_col + kc * 8]);
                ldsm_x4(ad, af[mt]);
            }
            #pragma unroll
            for (int p = 0; p < 4; p++) {
                float t4[4];
                uint32_t ad = smem_u32(&bb[(b_row + p * 16) * GLD + b_col + kc * 8]);
                ldsm_x4(ad, t4);
                bf[p*2  ][0] = t4[0]; bf[p*2  ][1] = t4[1];
                bf[p*2+1][0] = t4[2]; bf[p*2+1][1] = t4[3];
            }
            #pragma unroll
            for (int mt = 0; mt < 4; mt++)
                #pragma unroll
                for (int nt = 0; nt < 8; nt++)
                    mma_tf32(acc[mt][nt], af[mt], bf[nt]);
        }
    };

    LDG(0);
    STS(0);
    __syncthreads();
    int cur = 0;
    for (int it = 1; it < NKT; it++) {
        LDG(it * GBK);
        MMA_ALL(cur);
        STS(cur ^ 1);
        __syncthreads();
        cur ^= 1;
    }
    MMA_ALL(cur);

    // ---- fused epilogues ----
    #pragma unroll
    for (int mt = 0; mt < 4; mt++) {
        #pragma unroll
        for (int nt = 0; nt < 8; nt++) {
            #pragma unroll
            for (int e = 0; e < 4; e++) {
                int gm = m0 + wm + mt * 16 + gid + ((e >> 1) ? 8 : 0);
                int gn = n0 + wn + nt * 8 + tig * 2 + (e & 1);
                float v = acc[mt][nt][e];
                if (MODE == 0) {
                    int b = gm / NTOK, n = gm % NTOK;
                    int s = gn / DIMC, r = gn % DIMC;
                    int h = r / HDIM,  d = r % HDIM;
                    size_t o = ((size_t)(b * NH + h) * NTOK + n) * HDIM + d;
                    if (s == 0)      g_q[o] = (v + P1[r]) * 0.125f;
                    else if (s == 1) g_k[o] = v;
                    else             g_v[o] = v + P2[r];
                } else {
                    C_[(size_t)gm * DIMC + gn] = v + P1[gn];
                }
            }
        }
    }
}

// ---------------- fused attention: S = QK^T + rpb -> softmax -> P V ----------
constexpr int NP        = 208;
constexpr int KS_STRIDE = 68;
constexpr int VT_STRIDE = 212;
constexpr int ATT_SMEM  = (NP * KS_STRIDE + HDIM * VT_STRIDE) * 4;

__global__ void __launch_bounds__(256, 1) attn_fused_k()
{
    const int z = blockIdx.x;
    const int h = z % NH;
    const int b = z / NH;
    const float* q   = g_q + (size_t)z * NTOK * HDIM;
    const float* kk  = g_k + (size_t)z * NTOK * HDIM;
    const float* vv  = g_v + (size_t)z * NTOK * HDIM;
    const float* rpb = g_rpb + (size_t)h * NTOK * NTOK;

    extern __shared__ float sm[];
    float* ks = sm;
    float* vT = sm + NP * KS_STRIDE;

    const int tid = threadIdx.x;

    for (int idx = tid; idx < NP * 16; idx += 256) {
        int tok = idx >> 4, d4 = (idx & 15) * 4;
        float4 val = make_float4(0.f, 0.f, 0.f, 0.f);
        if (tok < NTOK) val = *(const float4*)&kk[tok * HDIM + d4];
        ks[tok * KS_STRIDE + d4 + 0] = f2tf32(val.x);
        ks[tok * KS_STRIDE + d4 + 1] = f2tf32(val.y);
        ks[tok * KS_STRIDE + d4 + 2] = f2tf32(val.z);
        ks[tok * KS_STRIDE + d4 + 3] = f2tf32(val.w);
    }
    for (int idx = tid; idx < NP * 16; idx += 256) {
        int tok = idx >> 4, d4 = (idx & 15) * 4;
        float4 val = make_float4(0.f, 0.f, 0.f, 0.f);
        if (tok < NTOK) val = *(const float4*)&vv[tok * HDIM + d4];
        vT[(d4 + 0) * VT_STRIDE + tok] = f2tf32(val.x);
        vT[(d4 + 1) * VT_STRIDE + tok] = f2tf32(val.y);
        vT[(d4 + 2) * VT_STRIDE + tok] = f2tf32(val.z);
        vT[(d4 + 3) * VT_STRIDE + tok] = f2tf32(val.w);
    }
    __syncthreads();

    const int w = tid >> 5, lane = tid & 31, gid = lane >> 2, tig = lane & 3;

    for (int r = 0; r < 2; r++) {
        const int t = w + 8 * r;
        if (t >= 13) break;
        const int m0 = t * 16;
        const int mA = m0 + gid;
        const int mB = m0 + gid + 8;

        float aq[8][4];
        #pragma unroll
        for (int kt = 0; kt < 8; kt++) {
            int c0 = kt * 8 + tig, c1 = c0 + 4;
            aq[kt][0] = (mA < NTOK) ? f2tf32(q[mA * HDIM + c0]) : 0.f;
            aq[kt][1] = (mB < NTOK) ? f2tf32(q[mB * HDIM + c0]) : 0.f;
            aq[kt][2] = (mA < NTOK) ? f2tf32(q[mA * HDIM + c1]) : 0.f;
            aq[kt][3] = (mB < NTOK) ? f2tf32(q[mB * HDIM + c1]) : 0.f;
        }

        float acc[26][4];
        #pragma unroll
        for (int nt = 0; nt < 26; nt++)
            acc[nt][0] = acc[nt][1] = acc[nt][2] = acc[nt][3] = 0.f;
        #pragma unroll
        for (int nt = 0; nt < 26; nt++) {
            const int n = nt * 8 + gid;
            #pragma unroll
            for (int kt = 0; kt < 8; kt++) {
                float bk[2];
                bk[0] = ks[n * KS_STRIDE + kt * 8 + tig];
                bk[1] = ks[n * KS_STRIDE + kt * 8 + tig + 4];
                mma_tf32(acc[nt], aq[kt], bk);
            }
        }

        const float* rA = rpb + (size_t)min(mA, NTOK - 1) * NTOK;
        const float* rB = rpb + (size_t)min(mB, NTOK - 1) * NTOK;
        float mx0 = -1e30f, mx1 = -1e30f;
        #pragma unroll
        for (int nt = 0; nt < 26; nt++) {
            int c0 = nt * 8 + tig * 2, c1 = c0 + 1;
            acc[nt][0] = (c0 < NTOK) ? acc[nt][0] + rA[c0] : -1e30f;
            acc[nt][1] = (c1 < NTOK) ? acc[nt][1] + rA[c1] : -1e30f;
            acc[nt][2] = (c0 < NTOK) ? acc[nt][2] + rB[c0] : -1e30f;
            acc[nt][3] = (c1 < NTOK) ? acc[nt][3] + rB[c1] : -1e30f;
            mx0 = fmaxf(mx0, fmaxf(acc[nt][0], acc[nt][1]));
            mx1 = fmaxf(mx1, fmaxf(acc[nt][2], acc[nt][3]));
        }
        #pragma unroll
        for (int o = 1; o <= 2; o <<= 1) {
            mx0 = fmaxf(mx0, __shfl_xor_sync(~0u, mx0, o));
            mx1 = fmaxf(mx1, __shfl_xor_sync(~0u, mx1, o));
        }
        float s0 = 0.f, s1 = 0.f;
        #pragma unroll
        for (int nt = 0; nt < 26; nt++) {
            acc[nt][0] = __expf(acc[nt][0] - mx0);
            acc[nt][1] = __expf(acc[nt][1] - mx0);
            acc[nt][2] = __expf(acc[nt][2] - mx1);
            acc[nt][3] = __expf(acc[nt][3] - mx1);
            s0 += acc[nt][0] + acc[nt][1];
            s1 += acc[nt][2] + acc[nt][3];
        }
        #pragma unroll
        for (int o = 1; o <= 2; o <<= 1) {
            s0 += __shfl_xor_sync(~0u, s0, o);
            s1 += __shfl_xor_sync(~0u, s1, o);
        }
        const float i0 = 1.f / s0, i1 = 1.f / s1;
        #pragma unroll
        for (int nt = 0; nt < 26; nt++) {
            acc[nt][0] *= i0; acc[nt][1] *= i0;
            acc[nt][2] *= i1; acc[nt][3] *= i1;
        }

        float acc2[8][4];
        #pragma unroll
        for (int nt = 0; nt < 8; nt++)
            acc2[nt][0] = acc2[nt][1] = acc2[nt][2] = acc2[nt][3] = 0.f;

        const int src0 = (lane & ~3) | (tig >> 1);
        const int src1 = src0 + 2;
        const bool odd = tig & 1;
        #pragma unroll
        for (int kt = 0; kt < 26; kt++) {
            float v00 = __shfl_sync(~0u, acc[kt][0], src0);
            float v01 = __shfl_sync(~0u, acc[kt][1], src0);
            float v02 = __shfl_sync(~0u, acc[kt][2], src0);
            float v03 = __shfl_sync(~0u, acc[kt][3], src0);
            float w00 = __shfl_sync(~0u, acc[kt][0], src1);
            float w01 = __shfl_sync(~0u, acc[kt][1], src1);
            float w02 = __shfl_sync(~0u, acc[kt][2], src1);
            float w03 = __shfl_sync(~0u, acc[kt][3], src1);
            float aP[4];
            aP[0] = f2tf32(odd ? v01 : v00);
            aP[1] = f2tf32(odd ? v03 : v02);
            aP[2] = f2tf32(odd ? w01 : w00);
            aP[3] = f2tf32(odd ? w03 : w02);
            #pragma unroll
            for (int nt = 0; nt < 8; nt++) {
                float bv[2];
                bv[0] = vT[(nt * 8 + gid) * VT_STRIDE + kt * 8 + tig];
                bv[1] = vT[(nt * 8 + gid) * VT_STRIDE + kt * 8 + tig + 4];
                mma_tf32(acc2[nt], aP, bv);
            }
        }

        #pragma unroll
        for (int nt = 0; nt < 8; nt++) {
            int d0 = nt * 8 + tig * 2;
            if (mA < NTOK) {
                float* o = &g_o[((size_t)(b * NTOK + mA)) * DIMC + h * HDIM + d0];
                o[0] = acc2[nt][0]; o[1] = acc2[nt][1];
            }
            if (mB < NTOK) {
                float* o = &g_o[((size_t)(b * NTOK + mB)) * DIMC + h * HDIM + d0];
                o[0] = acc2[nt][2]; o[1] = acc2[nt][3];
            }
        }
    }
}

// ---------------- launch ----------------
extern "C" void kernel_launch(void* const* d_in, const int* in_sizes, int n_in,
                              void* d_out, int out_size)
{
    const float* x = nullptr; const float* qkv_w = nullptr;
    const float* proj_w = nullptr; const float* rpb_table = nullptr;
    const int*   rel_idx = nullptr;
    const float* bias768[3] = {nullptr, nullptr, nullptr};
    int nbias = 0;
    for (int i = 0; i < n_in; i++) {
        switch (in_sizes[i]) {
            case MROWS * DIMC:    x         = (const float*)d_in[i]; break;
            case 3 * DIMC * DIMC: qkv_w     = (const float*)d_in[i]; break;
            case DIMC * DIMC:     proj_w    = (const float*)d_in[i]; break;
            case NTOK * NTOK:     rel_idx   = (const int*)d_in[i];   break;
            case 732 * NH:        rpb_table = (const float*)d_in[i]; break;
            case DIMC:            if (nbias < 3) bias768[nbias++] = (const float*)d_in[i]; break;
            default: break;
        }
    }
    const float* q_bias = bias768[0];
    const float* v_bias = bias768[1];
    const float* proj_b = bias768[2];
    float* out = (float*)d_out;

    cudaFuncSetAttribute(attn_fused_k, cudaFuncAttributeMaxDynamicSharedMemorySize, ATT_SMEM);
    cudaFuncSetAttribute(gemm_tc<0>, cudaFuncAttributeMaxDynamicSharedMemorySize, GEMM_SMEM);
    cudaFuncSetAttribute(gemm_tc<3>, cudaFuncAttributeMaxDynamicSharedMemorySize, GEMM_SMEM);

    rpb_expand_k<<<(NTOK * NTOK + 255) / 256, 256>>>(rel_idx, rpb_table);

    // 1) QKV projection: grid (2304/128, 25216/128)
    gemm_tc<0><<<dim3(18, 197), 128, GEMM_SMEM>>>(x, qkv_w, q_bias, v_bias, nullptr);

    // 2) fused attention
    attn_fused_k<<<NBH, 256, ATT_SMEM>>>();

    // 3) final projection + bias: grid (768/128, 197)
    gemm_tc<3><<<dim3(6, 197), 128, GEMM_SMEM>>>(nullptr, proj_w, proj_b, nullptr, out);
}

// round 10
// speedup vs baseline: 1.0926x; 1.0091x over previous
#include <cuda_runtime.h>
#include <cstdint>

// ---------------- problem constants ----------------
constexpr int NTOK  = 197;
constexpr int DIMC  = 768;
constexpr int NH    = 12;
constexpr int HDIM  = 64;
constexpr int NB    = 128;
constexpr int MROWS = NB * NTOK;    // 25216
constexpr int NBH   = NB * NH;      // 1536

// ---------------- scratch (device globals) ----------------
__device__ float g_q[(size_t)NBH * NTOK * HDIM];
__device__ float g_k[(size_t)NBH * NTOK * HDIM];
__device__ float g_v[(size_t)NBH * NTOK * HDIM];
__device__ float g_o[(size_t)MROWS * DIMC];
__device__ float g_rpb[NH * NTOK * NTOK];

// ---------------- helpers ----------------
__device__ __forceinline__ float f2tf32(float x) {
    unsigned u;
    asm("cvt.rna.tf32.f32 %0, %1;" : "=r"(u) : "f"(x));
    return __uint_as_float(u);
}

__device__ __forceinline__ void mma_tf32(float c[4], const float a[4], const float b[2]) {
    asm volatile(
        "mma.sync.aligned.m16n8k8.row.col.f32.tf32.tf32.f32 "
        "{%0,%1,%2,%3}, {%4,%5,%6,%7}, {%8,%9}, {%0,%1,%2,%3};"
        : "+f"(c[0]), "+f"(c[1]), "+f"(c[2]), "+f"(c[3])
        : "r"(__float_as_uint(a[0])), "r"(__float_as_uint(a[1])),
          "r"(__float_as_uint(a[2])), "r"(__float_as_uint(a[3])),
          "r"(__float_as_uint(b[0])), "r"(__float_as_uint(b[1])));
}

__device__ __forceinline__ void ldsm_x4(uint32_t addr, float d[4]) {
    uint32_t r0, r1, r2, r3;
    asm volatile("ldmatrix.sync.aligned.m8n8.x4.shared.b16 {%0,%1,%2,%3}, [%4];"
                 : "=r"(r0), "=r"(r1), "=r"(r2), "=r"(r3) : "r"(addr));
    d[0] = __uint_as_float(r0); d[1] = __uint_as_float(r1);
    d[2] = __uint_as_float(r2); d[3] = __uint_as_float(r3);
}

__device__ __forceinline__ uint32_t smem_u32(const void* p) {
    return (uint32_t)__cvta_generic_to_shared(p);
}

// ---------------- rpb gather expansion ----------------
__global__ void rpb_expand_k(const int* __restrict__ rel_idx,
                             const float* __restrict__ table)
{
    int ij = blockIdx.x * 256 + threadIdx.x;
    if (ij >= NTOK * NTOK) return;
    int rel = rel_idx[ij];
    #pragma unroll
    for (int h = 0; h < NH; h++)
        g_rpb[h * NTOK * NTOK + ij] = table[rel * NH + h];
}

// ---------------- TF32 GEMM: 128x128 block, 4 warps of 64x64, 2 CTAs/SM ------
// (unchanged from round 8 — proven 1198us configuration)
constexpr int GBM = 128, GBN = 128, GBK = 16, GLD = 20;
constexpr int GEMM_SMEM = 2 * (GBM + GBN) * GLD * 4;   // 40960 B

template<int MODE>
__global__ void __launch_bounds__(128, 2) gemm_tc(const float* __restrict__ A_,
                                                  const float* __restrict__ B_,
                                                  const float* __restrict__ P1,
                                                  const float* __restrict__ P2,
                                                  float* __restrict__ C_)
{
    constexpr int Kdim = DIMC;
    constexpr int NKT  = Kdim / GBK;               // 48

    const float* A  = (MODE == 3) ? (const float*)g_o : A_;
    const float* Bm = B_;

    const int m0  = blockIdx.y * GBM;
    const int n0  = blockIdx.x * GBN;
    const int tid = threadIdx.x;
    const int w    = tid >> 5, lane = tid & 31;
    const int gid  = lane >> 2, tig = lane & 3;
    const int wm   = (w & 1) * 64;
    const int wn   = (w >> 1) * 64;

    extern __shared__ float smg[];
    float* As = smg;                         // [2][GBM*GLD]
    float* Bs = smg + 2 * GBM * GLD;         // [2][GBN*GLD]

    const int sr = tid >> 2;            // 0..31
    const int sc = (tid & 3) * 4;

    const float* pa = &A [(size_t)(m0 + sr) * Kdim + sc];
    const float* pb = &Bm[(size_t)(n0 + sr) * Kdim + sc];

    float4 va[4], vb[4];
    float acc[4][8][4] = {};

    const int lt   = lane >> 3;
    const int li   = lane & 7;
    const int a_row = wm + (lt & 1) * 8 + li;
    const int a_col = (lt >> 1) * 4;
    const int b_row = wn + (lt >> 1) * 8 + li;
    const int b_col = (lt & 1) * 4;

    auto LDG = [&](int kt) {
        #pragma unroll
        for (int r = 0; r < 4; r++) {
            va[r] = *(const float4*)(pa + (size_t)(r * 32) * Kdim + kt);
            vb[r] = *(const float4*)(pb + (size_t)(r * 32) * Kdim + kt);
        }
    };
    auto STS = [&](int buf) {
        float* ab = As + buf * GBM * GLD;
        float* bb = Bs + buf * GBN * GLD;
        #pragma unroll
        for (int r = 0; r < 4; r++) {
            float4 t;
            t = make_float4(f2tf32(va[r].x), f2tf32(va[r].y), f2tf32(va[r].z), f2tf32(va[r].w));
            *(float4*)&ab[(sr + r * 32) * GLD + sc] = t;
            t = make_float4(f2tf32(vb[r].x), f2tf32(vb[r].y), f2tf32(vb[r].z), f2tf32(vb[r].w));
            *(float4*)&bb[(sr + r * 32) * GLD + sc] = t;
        }
    };
    auto MMA_ALL = [&](int buf) {
        const float* ab = As + buf * GBM * GLD;
        const float* bb = Bs + buf * GBN * GLD;
        #pragma unroll
        for (int kc = 0; kc < 2; kc++) {
            float af[4][4], bf[8][2];
            #pragma unroll
            for (int mt = 0; mt < 4; mt++) {
                uint32_t ad = smem_u32(&ab[(a_row + mt * 16) * GLD + a_col + kc * 8]);
                ldsm_x4(ad, af[mt]);
            }
            #pragma unroll
            for (int p = 0; p < 4; p++) {
                float t4[4];
                uint32_t ad = smem_u32(&bb[(b_row + p * 16) * GLD + b_col + kc * 8]);
                ldsm_x4(ad, t4);
                bf[p*2  ][0] = t4[0]; bf[p*2  ][1] = t4[1];
                bf[p*2+1][0] = t4[2]; bf[p*2+1][1] = t4[3];
            }
            #pragma unroll
            for (int mt = 0; mt < 4; mt++)
                #pragma unroll
                for (int nt = 0; nt < 8; nt++)
                    mma_tf32(acc[mt][nt], af[mt], bf[nt]);
        }
    };

    LDG(0);
    STS(0);
    __syncthreads();
    int cur = 0;
    for (int it = 1; it < NKT; it++) {
        LDG(it * GBK);
        MMA_ALL(cur);
        STS(cur ^ 1);
        __syncthreads();
        cur ^= 1;
    }
    MMA_ALL(cur);

    #pragma unroll
    for (int mt = 0; mt < 4; mt++) {
        #pragma unroll
        for (int nt = 0; nt < 8; nt++) {
            #pragma unroll
            for (int e = 0; e < 4; e++) {
                int gm = m0 + wm + mt * 16 + gid + ((e >> 1) ? 8 : 0);
                int gn = n0 + wn + nt * 8 + tig * 2 + (e & 1);
                float v = acc[mt][nt][e];
                if (MODE == 0) {
                    int b = gm / NTOK, n = gm % NTOK;
                    int s = gn / DIMC, r = gn % DIMC;
                    int h = r / HDIM,  d = r % HDIM;
                    size_t o = ((size_t)(b * NH + h) * NTOK + n) * HDIM + d;
                    if (s == 0)      g_q[o] = (v + P1[r]) * 0.125f;
                    else if (s == 1) g_k[o] = v;
                    else             g_v[o] = v + P2[r];
                } else {
                    C_[(size_t)gm * DIMC + gn] = v + P1[gn];
                }
            }
        }
    }
}

// ---------------- fused attention: S = QK^T + rpb -> softmax -> P V ----------
// B-fragments for both GEMM phases now come from ldmatrix.x4 (same verified
// lane mapping as gemm_tc) instead of scalar LDS — ~35% fewer instructions.
constexpr int NP        = 208;
constexpr int KS_STRIDE = 68;    // row step 272B = 16B mod 128 -> LDSM conflict-free
constexpr int VT_STRIDE = 212;   // row step 848B = 80  mod 128 -> LDSM conflict-free
constexpr int ATT_SMEM  = (NP * KS_STRIDE + HDIM * VT_STRIDE) * 4;

__global__ void __launch_bounds__(256, 1) attn_fused_k()
{
    const int z = blockIdx.x;
    const int h = z % NH;
    const int b = z / NH;
    const float* q   = g_q + (size_t)z * NTOK * HDIM;
    const float* kk  = g_k + (size_t)z * NTOK * HDIM;
    const float* vv  = g_v + (size_t)z * NTOK * HDIM;
    const float* rpb = g_rpb + (size_t)h * NTOK * NTOK;

    extern __shared__ float sm[];
    float* ks = sm;
    float* vT = sm + NP * KS_STRIDE;

    const int tid = threadIdx.x;

    for (int idx = tid; idx < NP * 16; idx += 256) {
        int tok = idx >> 4, d4 = (idx & 15) * 4;
        float4 val = make_float4(0.f, 0.f, 0.f, 0.f);
        if (tok < NTOK) val = *(const float4*)&kk[tok * HDIM + d4];
        ks[tok * KS_STRIDE + d4 + 0] = f2tf32(val.x);
        ks[tok * KS_STRIDE + d4 + 1] = f2tf32(val.y);
        ks[tok * KS_STRIDE + d4 + 2] = f2tf32(val.z);
        ks[tok * KS_STRIDE + d4 + 3] = f2tf32(val.w);
    }
    for (int idx = tid; idx < NP * 16; idx += 256) {
        int tok = idx >> 4, d4 = (idx & 15) * 4;
        float4 val = make_float4(0.f, 0.f, 0.f, 0.f);
        if (tok < NTOK) val = *(const float4*)&vv[tok * HDIM + d4];
        vT[(d4 + 0) * VT_STRIDE + tok] = f2tf32(val.x);
        vT[(d4 + 1) * VT_STRIDE + tok] = f2tf32(val.y);
        vT[(d4 + 2) * VT_STRIDE + tok] = f2tf32(val.z);
        vT[(d4 + 3) * VT_STRIDE + tok] = f2tf32(val.w);
    }
    __syncthreads();

    const int w = tid >> 5, lane = tid & 31, gid = lane >> 2, tig = lane & 3;
    const int lt = lane >> 3, li = lane & 7;
    // LDSM B-side lane geometry (same as gemm_tc, wn = 0)
    const int bs_row = (lt >> 1) * 8 + li;   // + np*16
    const int bs_col = (lt & 1) * 4;         // + kt*8

    for (int r = 0; r < 2; r++) {
        const int t = w + 8 * r;
        if (t >= 13) break;
        const int m0 = t * 16;
        const int mA = m0 + gid;
        const int mB = m0 + gid + 8;

        float aq[8][4];
        #pragma unroll
        for (int kt = 0; kt < 8; kt++) {
            int c0 = kt * 8 + tig, c1 = c0 + 4;
            aq[kt][0] = (mA < NTOK) ? f2tf32(q[mA * HDIM + c0]) : 0.f;
            aq[kt][1] = (mB < NTOK) ? f2tf32(q[mB * HDIM + c0]) : 0.f;
            aq[kt][2] = (mA < NTOK) ? f2tf32(q[mA * HDIM + c1]) : 0.f;
            aq[kt][3] = (mB < NTOK) ? f2tf32(q[mB * HDIM + c1]) : 0.f;
        }

        // S = Q K^T via LDSM-fed B fragments (13 n-pairs x 8 k-chunks)
        float acc[26][4];
        #pragma unroll
        for (int nt = 0; nt < 26; nt++)
            acc[nt][0] = acc[nt][1] = acc[nt][2] = acc[nt][3] = 0.f;
        #pragma unroll
        for (int np = 0; np < 13; np++) {
            #pragma unroll
            for (int kt = 0; kt < 8; kt++) {
                float t4[4];
                uint32_t ad = smem_u32(&ks[(np * 16 + bs_row) * KS_STRIDE + bs_col + kt * 8]);
                ldsm_x4(ad, t4);
                float bk0[2] = { t4[0], t4[1] };
                float bk1[2] = { t4[2], t4[3] };
                mma_tf32(acc[np * 2    ], aq[kt], bk0);
                mma_tf32(acc[np * 2 + 1], aq[kt], bk1);
            }
        }

        const float* rA = rpb + (size_t)min(mA, NTOK - 1) * NTOK;
        const float* rB = rpb + (size_t)min(mB, NTOK - 1) * NTOK;
        float mx0 = -1e30f, mx1 = -1e30f;
        #pragma unroll
        for (int nt = 0; nt < 26; nt++) {
            int c0 = nt * 8 + tig * 2, c1 = c0 + 1;
            acc[nt][0] = (c0 < NTOK) ? acc[nt][0] + rA[c0] : -1e30f;
            acc[nt][1] = (c1 < NTOK) ? acc[nt][1] + rA[c1] : -1e30f;
            acc[nt][2] = (c0 < NTOK) ? acc[nt][2] + rB[c0] : -1e30f;
            acc[nt][3] = (c1 < NTOK) ? acc[nt][3] + rB[c1] : -1e30f;
            mx0 = fmaxf(mx0, fmaxf(acc[nt][0], acc[nt][1]));
            mx1 = fmaxf(mx1, fmaxf(acc[nt][2], acc[nt][3]));
        }
        #pragma unroll
        for (int o = 1; o <= 2; o <<= 1) {
            mx0 = fmaxf(mx0, __shfl_xor_sync(~0u, mx0, o));
            mx1 = fmaxf(mx1, __shfl_xor_sync(~0u, mx1, o));
        }
        float s0 = 0.f, s1 = 0.f;
        #pragma unroll
        for (int nt = 0; nt < 26; nt++) {
            acc[nt][0] = __expf(acc[nt][0] - mx0);
            acc[nt][1] = __expf(acc[nt][1] - mx0);
            acc[nt][2] = __expf(acc[nt][2] - mx1);
            acc[nt][3] = __expf(acc[nt][3] - mx1);
            s0 += acc[nt][0] + acc[nt][1];
            s1 += acc[nt][2] + acc[nt][3];
        }
        #pragma unroll
        for (int o = 1; o <= 2; o <<= 1) {
            s0 += __shfl_xor_sync(~0u, s0, o);
            s1 += __shfl_xor_sync(~0u, s1, o);
        }
        const float i0 = 1.f / s0, i1 = 1.f / s1;
        #pragma unroll
        for (int nt = 0; nt < 26; nt++) {
            acc[nt][0] *= i0; acc[nt][1] *= i0;
            acc[nt][2] *= i1; acc[nt][3] *= i1;
        }

        // O = P V via LDSM-fed B fragments (4 d-pairs x 26 k-chunks)
        float acc2[8][4];
        #pragma unroll
        for (int nt = 0; nt < 8; nt++)
            acc2[nt][0] = acc2[nt][1] = acc2[nt][2] = acc2[nt][3] = 0.f;

        const int src0 = (lane & ~3) | (tig >> 1);
        const int src1 = src0 + 2;
        const bool odd = tig & 1;
        #pragma unroll
        for (int kt = 0; kt < 26; kt++) {
            float v00 = __shfl_sync(~0u, acc[kt][0], src0);
            float v01 = __shfl_sync(~0u, acc[kt][1], src0);
            float v02 = __shfl_sync(~0u, acc[kt][2], src0);
            float v03 = __shfl_sync(~0u, acc[kt][3], src0);
            float w00 = __shfl_sync(~0u, acc[kt][0], src1);
            float w01 = __shfl_sync(~0u, acc[kt][1], src1);
            float w02 = __shfl_sync(~0u, acc[kt][2], src1);
            float w03 = __shfl_sync(~0u, acc[kt][3], src1);
            float aP[4];
            aP[0] = f2tf32(odd ? v01 : v00);
            aP[1] = f2tf32(odd ? v03 : v02);
            aP[2] = f2tf32(odd ? w01 : w00);
            aP[3] = f2tf32(odd ? w03 : w02);
            #pragma unroll
            for (int np = 0; np < 4; np++) {
                float t4[4];
                uint32_t ad = smem_u32(&vT[(np * 16 + bs_row) * VT_STRIDE + bs_col + kt * 8]);
                ldsm_x4(ad, t4);
                float bv0[2] = { t4[0], t4[1] };
                float bv1[2] = { t4[2], t4[3] };
                mma_tf32(acc2[np * 2    ], aP, bv0);
                mma_tf32(acc2[np * 2 + 1], aP, bv1);
            }
        }

        #pragma unroll
        for (int nt = 0; nt < 8; nt++) {
            int d0 = nt * 8 + tig * 2;
            if (mA < NTOK) {
                float* o = &g_o[((size_t)(b * NTOK + mA)) * DIMC + h * HDIM + d0];
                o[0] = acc2[nt][0]; o[1] = acc2[nt][1];
            }
            if (mB < NTOK) {
                float* o = &g_o[((size_t)(b * NTOK + mB)) * DIMC + h * HDIM + d0];
                o[0] = acc2[nt][2]; o[1] = acc2[nt][3];
            }
        }
    }
}

// ---------------- launch ----------------
extern "C" void kernel_launch(void* const* d_in, const int* in_sizes, int n_in,
                              void* d_out, int out_size)
{
    const float* x = nullptr; const float* qkv_w = nullptr;
    const float* proj_w = nullptr; const float* rpb_table = nullptr;
    const int*   rel_idx = nullptr;
    const float* bias768[3] = {nullptr, nullptr, nullptr};
    int nbias = 0;
    for (int i = 0; i < n_in; i++) {
        switch (in_sizes[i]) {
            case MROWS * DIMC:    x         = (const float*)d_in[i]; break;
            case 3 * DIMC * DIMC: qkv_w     = (const float*)d_in[i]; break;
            case DIMC * DIMC:     proj_w    = (const float*)d_in[i]; break;
            case NTOK * NTOK:     rel_idx   = (const int*)d_in[i];   break;
            case 732 * NH:        rpb_table = (const float*)d_in[i]; break;
            case DIMC:            if (nbias < 3) bias768[nbias++] = (const float*)d_in[i]; break;
            default: break;
        }
    }
    const float* q_bias = bias768[0];
    const float* v_bias = bias768[1];
    const float* proj_b = bias768[2];
    float* out = (float*)d_out;

    cudaFuncSetAttribute(attn_fused_k, cudaFuncAttributeMaxDynamicSharedMemorySize, ATT_SMEM);
    cudaFuncSetAttribute(gemm_tc<0>, cudaFuncAttributeMaxDynamicSharedMemorySize, GEMM_SMEM);
    cudaFuncSetAttribute(gemm_tc<3>, cudaFuncAttributeMaxDynamicSharedMemorySize, GEMM_SMEM);

    rpb_expand_k<<<(NTOK * NTOK + 255) / 256, 256>>>(rel_idx, rpb_table);

    // 1) QKV projection: grid (2304/128, 25216/128)
    gemm_tc<0><<<dim3(18, 197), 128, GEMM_SMEM>>>(x, qkv_w, q_bias, v_bias, nullptr);

    // 2) fused attention
    attn_fused_k<<<NBH, 256, ATT_SMEM>>>();

    // 3) final projection + bias: grid (768/128, 197)
    gemm_tc<3><<<dim3(6, 197), 128, GEMM_SMEM>>>(nullptr, proj_w, proj_b, nullptr, out);
}

// round 11
// speedup vs baseline: 1.1770x; 1.0773x over previous
#include <cuda_runtime.h>
#include <cstdint>

// ---------------- problem constants ----------------
constexpr int NTOK  = 197;
constexpr int DIMC  = 768;
constexpr int NH    = 12;
constexpr int HDIM  = 64;
constexpr int NB    = 128;
constexpr int MROWS = NB * NTOK;    // 25216
constexpr int NBH   = NB * NH;      // 1536

// ---------------- scratch (device globals) ----------------
__device__ float g_q[(size_t)NBH * NTOK * HDIM];
__device__ float g_k[(size_t)NBH * NTOK * HDIM];
__device__ float g_v[(size_t)NBH * NTOK * HDIM];
__device__ float g_o[(size_t)MROWS * DIMC];      // written TF32-rounded by attention
__device__ float g_rpb[NH * NTOK * NTOK];
__device__ float g_xc[(size_t)MROWS * DIMC];     // tf32-rounded x
__device__ float g_wc[(size_t)3 * DIMC * DIMC];  // tf32-rounded qkv_w
__device__ float g_pwc[(size_t)DIMC * DIMC];     // tf32-rounded proj_w

// ---------------- helpers ----------------
__device__ __forceinline__ float f2tf32(float x) {
    unsigned u;
    asm("cvt.rna.tf32.f32 %0, %1;" : "=r"(u) : "f"(x));
    return __uint_as_float(u);
}

__device__ __forceinline__ void mma_tf32(float c[4], const float a[4], const float b[2]) {
    asm volatile(
        "mma.sync.aligned.m16n8k8.row.col.f32.tf32.tf32.f32 "
        "{%0,%1,%2,%3}, {%4,%5,%6,%7}, {%8,%9}, {%0,%1,%2,%3};"
        : "+f"(c[0]), "+f"(c[1]), "+f"(c[2]), "+f"(c[3])
        : "r"(__float_as_uint(a[0])), "r"(__float_as_uint(a[1])),
          "r"(__float_as_uint(a[2])), "r"(__float_as_uint(a[3])),
          "r"(__float_as_uint(b[0])), "r"(__float_as_uint(b[1])));
}

__device__ __forceinline__ void ldsm_x4(uint32_t addr, float d[4]) {
    uint32_t r0, r1, r2, r3;
    asm volatile("ldmatrix.sync.aligned.m8n8.x4.shared.b16 {%0,%1,%2,%3}, [%4];"
                 : "=r"(r0), "=r"(r1), "=r"(r2), "=r"(r3) : "r"(addr));
    d[0] = __uint_as_float(r0); d[1] = __uint_as_float(r1);
    d[2] = __uint_as_float(r2); d[3] = __uint_as_float(r3);
}

__device__ __forceinline__ uint32_t smem_u32(const void* p) {
    return (uint32_t)__cvta_generic_to_shared(p);
}

__device__ __forceinline__ void cp_async16(uint32_t dst, const void* src) {
    asm volatile("cp.async.cg.shared.global [%0], [%1], 16;"
                 :: "r"(dst), "l"(src) : "memory");
}
__device__ __forceinline__ void cp_commit() {
    asm volatile("cp.async.commit_group;" ::: "memory");
}
__device__ __forceinline__ void cp_wait1() {
    asm volatile("cp.async.wait_group 1;" ::: "memory");
}

// ---------------- prepass: tf32-round inputs into device copies ----------------
__global__ void cvt_k(const float* __restrict__ src, int n4, int which)
{
    float* dst = (which == 0) ? g_xc : (which == 1) ? g_wc : g_pwc;
    int i = blockIdx.x * 256 + threadIdx.x;
    if (i >= n4) return;
    float4 v = ((const float4*)src)[i];
    ((float4*)dst)[i] = make_float4(f2tf32(v.x), f2tf32(v.y), f2tf32(v.z), f2tf32(v.w));
}

// ---------------- rpb gather expansion ----------------
__global__ void rpb_expand_k(const int* __restrict__ rel_idx,
                             const float* __restrict__ table)
{
    int ij = blockIdx.x * 256 + threadIdx.x;
    if (ij >= NTOK * NTOK) return;
    int rel = rel_idx[ij];
    #pragma unroll
    for (int h = 0; h < NH; h++)
        g_rpb[h * NTOK * NTOK + ij] = table[rel * NH + h];
}

// ---------------- TF32 GEMM: 128x128 block, cp.async 3-stage pipeline --------
// MODE 0: QKV  [25216,2304] = g_xc @ g_wc^T (+bias, scale, scatter q/k/v)
// MODE 3: proj [25216,768]  = g_o  @ g_pwc^T (+bias)   (g_o already tf32)
constexpr int GBM = 128, GBN = 128, GBK = 16, GLD = 20, NSTG = 3;
constexpr int GEMM_SMEM = NSTG * (GBM + GBN) * GLD * 4;   // 61440 B

template<int MODE>
__global__ void __launch_bounds__(128, 2) gemm_tc(const float* __restrict__ P1,
                                                  const float* __restrict__ P2,
                                                  float* __restrict__ C_)
{
    constexpr int Kdim = DIMC;
    constexpr int NKT  = Kdim / GBK;               // 48

    const float* A  = (MODE == 3) ? (const float*)g_o : (const float*)g_xc;
    const float* Bm = (MODE == 3) ? (const float*)g_pwc : (const float*)g_wc;

    const int m0  = blockIdx.y * GBM;
    const int n0  = blockIdx.x * GBN;
    const int tid = threadIdx.x;
    const int w    = tid >> 5, lane = tid & 31;
    const int gid  = lane >> 2, tig = lane & 3;
    const int wm   = (w & 1) * 64;
    const int wn   = (w >> 1) * 64;

    extern __shared__ float smg[];
    float* As = smg;                              // [NSTG][GBM*GLD]
    float* Bs = smg + NSTG * GBM * GLD;           // [NSTG][GBN*GLD]

    const int sr = tid >> 2;            // 0..31
    const int sc = (tid & 3) * 4;

    const float* pa = &A [(size_t)(m0 + sr) * Kdim + sc];
    const float* pb = &Bm[(size_t)(n0 + sr) * Kdim + sc];

    float acc[4][8][4] = {};

    const int lt   = lane >> 3;
    const int li   = lane & 7;
    const int a_row = wm + (lt & 1) * 8 + li;
    const int a_col = (lt >> 1) * 4;
    const int b_row = wn + (lt >> 1) * 8 + li;
    const int b_col = (lt & 1) * 4;

    auto STAGE = [&](int kt_idx, int buf) {
        float* ab = As + buf * GBM * GLD;
        float* bb = Bs + buf * GBN * GLD;
        const int kt = kt_idx * GBK;
        #pragma unroll
        for (int r = 0; r < 4; r++) {
            cp_async16(smem_u32(&ab[(sr + r * 32) * GLD + sc]),
                       pa + (size_t)(r * 32) * Kdim + kt);
            cp_async16(smem_u32(&bb[(sr + r * 32) * GLD + sc]),
                       pb + (size_t)(r * 32) * Kdim + kt);
        }
    };
    auto MMA_ALL = [&](int buf) {
        const float* ab = As + buf * GBM * GLD;
        const float* bb = Bs + buf * GBN * GLD;
        #pragma unroll
        for (int kc = 0; kc < 2; kc++) {
            float af[4][4], bf[8][2];
            #pragma unroll
            for (int mt = 0; mt < 4; mt++) {
                uint32_t ad = smem_u32(&ab[(a_row + mt * 16) * GLD + a_col + kc * 8]);
                ldsm_x4(ad, af[mt]);
            }
            #pragma unroll
            for (int p = 0; p < 4; p++) {
                float t4[4];
                uint32_t ad = smem_u32(&bb[(b_row + p * 16) * GLD + b_col + kc * 8]);
                ldsm_x4(ad, t4);
                bf[p*2  ][0] = t4[0]; bf[p*2  ][1] = t4[1];
                bf[p*2+1][0] = t4[2]; bf[p*2+1][1] = t4[3];
            }
            #pragma unroll
            for (int mt = 0; mt < 4; mt++)
                #pragma unroll
                for (int nt = 0; nt < 8; nt++)
                    mma_tf32(acc[mt][nt], af[mt], bf[nt]);
        }
    };

    // prologue: tiles 0 and 1 in flight
    STAGE(0, 0); cp_commit();
    STAGE(1, 1); cp_commit();
    for (int it = 0; it < NKT; it++) {
        cp_wait1();                 // tile `it` resident (1 newer group may pend)
        __syncthreads();            // all warps done with MMA(it-1) -> buf reusable
        if (it + 2 < NKT) STAGE(it + 2, (it + 2) % NSTG);
        cp_commit();                // empty group when no stage issued (keeps count)
        MMA_ALL(it % NSTG);
    }

    // ---- fused epilogues (unchanged) ----
    #pragma unroll
    for (int mt = 0; mt < 4; mt++) {
        #pragma unroll
        for (int nt = 0; nt < 8; nt++) {
            #pragma unroll
            for (int e = 0; e < 4; e++) {
                int gm = m0 + wm + mt * 16 + gid + ((e >> 1) ? 8 : 0);
                int gn = n0 + wn + nt * 8 + tig * 2 + (e & 1);
                float v = acc[mt][nt][e];
                if (MODE == 0) {
                    int b = gm / NTOK, n = gm % NTOK;
                    int s = gn / DIMC, r = gn % DIMC;
                    int h = r / HDIM,  d = r % HDIM;
                    size_t o = ((size_t)(b * NH + h) * NTOK + n) * HDIM + d;
                    if (s == 0)      g_q[o] = (v + P1[r]) * 0.125f;
                    else if (s == 1) g_k[o] = v;
                    else             g_v[o] = v + P2[r];
                } else {
                    C_[(size_t)gm * DIMC + gn] = v + P1[gn];
                }
            }
        }
    }
}

// ---------------- fused attention (unchanged math; g_o stores tf32-rounded) --
constexpr int NP        = 208;
constexpr int KS_STRIDE = 68;
constexpr int VT_STRIDE = 212;
constexpr int ATT_SMEM  = (NP * KS_STRIDE + HDIM * VT_STRIDE) * 4;

__global__ void __launch_bounds__(256, 1) attn_fused_k()
{
    const int z = blockIdx.x;
    const int h = z % NH;
    const int b = z / NH;
    const float* q   = g_q + (size_t)z * NTOK * HDIM;
    const float* kk  = g_k + (size_t)z * NTOK * HDIM;
    const float* vv  = g_v + (size_t)z * NTOK * HDIM;
    const float* rpb = g_rpb + (size_t)h * NTOK * NTOK;

    extern __shared__ float sm[];
    float* ks = sm;
    float* vT = sm + NP * KS_STRIDE;

    const int tid = threadIdx.x;

    for (int idx = tid; idx < NP * 16; idx += 256) {
        int tok = idx >> 4, d4 = (idx & 15) * 4;
        float4 val = make_float4(0.f, 0.f, 0.f, 0.f);
        if (tok < NTOK) val = *(const float4*)&kk[tok * HDIM + d4];
        ks[tok * KS_STRIDE + d4 + 0] = f2tf32(val.x);
        ks[tok * KS_STRIDE + d4 + 1] = f2tf32(val.y);
        ks[tok * KS_STRIDE + d4 + 2] = f2tf32(val.z);
        ks[tok * KS_STRIDE + d4 + 3] = f2tf32(val.w);
    }
    for (int idx = tid; idx < NP * 16; idx += 256) {
        int tok = idx >> 4, d4 = (idx & 15) * 4;
        float4 val = make_float4(0.f, 0.f, 0.f, 0.f);
        if (tok < NTOK) val = *(const float4*)&vv[tok * HDIM + d4];
        vT[(d4 + 0) * VT_STRIDE + tok] = f2tf32(val.x);
        vT[(d4 + 1) * VT_STRIDE + tok] = f2tf32(val.y);
        vT[(d4 + 2) * VT_STRIDE + tok] = f2tf32(val.z);
        vT[(d4 + 3) * VT_STRIDE + tok] = f2tf32(val.w);
    }
    __syncthreads();

    const int w = tid >> 5, lane = tid & 31, gid = lane >> 2, tig = lane & 3;
    const int lt = lane >> 3, li = lane & 7;
    const int bs_row = (lt >> 1) * 8 + li;
    const int bs_col = (lt & 1) * 4;

    for (int r = 0; r < 2; r++) {
        const int t = w + 8 * r;
        if (t >= 13) break;
        const int m0 = t * 16;
        const int mA = m0 + gid;
        const int mB = m0 + gid + 8;

        float aq[8][4];
        #pragma unroll
        for (int kt = 0; kt < 8; kt++) {
            int c0 = kt * 8 + tig, c1 = c0 + 4;
            aq[kt][0] = (mA < NTOK) ? f2tf32(q[mA * HDIM + c0]) : 0.f;
            aq[kt][1] = (mB < NTOK) ? f2tf32(q[mB * HDIM + c0]) : 0.f;
            aq[kt][2] = (mA < NTOK) ? f2tf32(q[mA * HDIM + c1]) : 0.f;
            aq[kt][3] = (mB < NTOK) ? f2tf32(q[mB * HDIM + c1]) : 0.f;
        }

        float acc[26][4];
        #pragma unroll
        for (int nt = 0; nt < 26; nt++)
            acc[nt][0] = acc[nt][1] = acc[nt][2] = acc[nt][3] = 0.f;
        #pragma unroll
        for (int np = 0; np < 13; np++) {
            #pragma unroll
            for (int kt = 0; kt < 8; kt++) {
                float t4[4];
                uint32_t ad = smem_u32(&ks[(np * 16 + bs_row) * KS_STRIDE + bs_col + kt * 8]);
                ldsm_x4(ad, t4);
                float bk0[2] = { t4[0], t4[1] };
                float bk1[2] = { t4[2], t4[3] };
                mma_tf32(acc[np * 2    ], aq[kt], bk0);
                mma_tf32(acc[np * 2 + 1], aq[kt], bk1);
            }
        }

        const float* rA = rpb + (size_t)min(mA, NTOK - 1) * NTOK;
        const float* rB = rpb + (size_t)min(mB, NTOK - 1) * NTOK;
        float mx0 = -1e30f, mx1 = -1e30f;
        #pragma unroll
        for (int nt = 0; nt < 26; nt++) {
            int c0 = nt * 8 + tig * 2, c1 = c0 + 1;
            acc[nt][0] = (c0 < NTOK) ? acc[nt][0] + rA[c0] : -1e30f;
            acc[nt][1] = (c1 < NTOK) ? acc[nt][1] + rA[c1] : -1e30f;
            acc[nt][2] = (c0 < NTOK) ? acc[nt][2] + rB[c0] : -1e30f;
            acc[nt][3] = (c1 < NTOK) ? acc[nt][3] + rB[c1] : -1e30f;
            mx0 = fmaxf(mx0, fmaxf(acc[nt][0], acc[nt][1]));
            mx1 = fmaxf(mx1, fmaxf(acc[nt][2], acc[nt][3]));
        }
        #pragma unroll
        for (int o = 1; o <= 2; o <<= 1) {
            mx0 = fmaxf(mx0, __shfl_xor_sync(~0u, mx0, o));
            mx1 = fmaxf(mx1, __shfl_xor_sync(~0u, mx1, o));
        }
        float s0 = 0.f, s1 = 0.f;
        #pragma unroll
        for (int nt = 0; nt < 26; nt++) {
            acc[nt][0] = __expf(acc[nt][0] - mx0);
            acc[nt][1] = __expf(acc[nt][1] - mx0);
            acc[nt][2] = __expf(acc[nt][2] - mx1);
            acc[nt][3] = __expf(acc[nt][3] - mx1);
            s0 += acc[nt][0] + acc[nt][1];
            s1 += acc[nt][2] + acc[nt][3];
        }
        #pragma unroll
        for (int o = 1; o <= 2; o <<= 1) {
            s0 += __shfl_xor_sync(~0u, s0, o);
            s1 += __shfl_xor_sync(~0u, s1, o);
        }
        const float i0 = 1.f / s0, i1 = 1.f / s1;
        #pragma unroll
        for (int nt = 0; nt < 26; nt++) {
            acc[nt][0] *= i0; acc[nt][1] *= i0;
            acc[nt][2] *= i1; acc[nt][3] *= i1;
        }

        float acc2[8][4];
        #pragma unroll
        for (int nt = 0; nt < 8; nt++)
            acc2[nt][0] = acc2[nt][1] = acc2[nt][2] = acc2[nt][3] = 0.f;

        const int src0 = (lane & ~3) | (tig >> 1);
        const int src1 = src0 + 2;
        const bool odd = tig & 1;
        #pragma unroll
        for (int kt = 0; kt < 26; kt++) {
            float v00 = __shfl_sync(~0u, acc[kt][0], src0);
            float v01 = __shfl_sync(~0u, acc[kt][1], src0);
            float v02 = __shfl_sync(~0u, acc[kt][2], src0);
            float v03 = __shfl_sync(~0u, acc[kt][3], src0);
            float w00 = __shfl_sync(~0u, acc[kt][0], src1);
            float w01 = __shfl_sync(~0u, acc[kt][1], src1);
            float w02 = __shfl_sync(~0u, acc[kt][2], src1);
            float w03 = __shfl_sync(~0u, acc[kt][3], src1);
            float aP[4];
            aP[0] = f2tf32(odd ? v01 : v00);
            aP[1] = f2tf32(odd ? v03 : v02);
            aP[2] = f2tf32(odd ? w01 : w00);
            aP[3] = f2tf32(odd ? w03 : w02);
            #pragma unroll
            for (int np = 0; np < 4; np++) {
                float t4[4];
                uint32_t ad = smem_u32(&vT[(np * 16 + bs_row) * VT_STRIDE + bs_col + kt * 8]);
                ldsm_x4(ad, t4);
                float bv0[2] = { t4[0], t4[1] };
                float bv1[2] = { t4[2], t4[3] };
                mma_tf32(acc2[np * 2    ], aP, bv0);
                mma_tf32(acc2[np * 2 + 1], aP, bv1);
            }
        }

        // store tf32-rounded (numerically identical to proj-side conversion)
        #pragma unroll
        for (int nt = 0; nt < 8; nt++) {
            int d0 = nt * 8 + tig * 2;
            if (mA < NTOK) {
                float* o = &g_o[((size_t)(b * NTOK + mA)) * DIMC + h * HDIM + d0];
                o[0] = f2tf32(acc2[nt][0]); o[1] = f2tf32(acc2[nt][1]);
            }
            if (mB < NTOK) {
                float* o = &g_o[((size_t)(b * NTOK + mB)) * DIMC + h * HDIM + d0];
                o[0] = f2tf32(acc2[nt][2]); o[1] = f2tf32(acc2[nt][3]);
            }
        }
    }
}

// ---------------- launch ----------------
extern "C" void kernel_launch(void* const* d_in, const int* in_sizes, int n_in,
                              void* d_out, int out_size)
{
    const float* x = nullptr; const float* qkv_w = nullptr;
    const float* proj_w = nullptr; const float* rpb_table = nullptr;
    const int*   rel_idx = nullptr;
    const float* bias768[3] = {nullptr, nullptr, nullptr};
    int nbias = 0;
    for (int i = 0; i < n_in; i++) {
        switch (in_sizes[i]) {
            case MROWS * DIMC:    x         = (const float*)d_in[i]; break;
            case 3 * DIMC * DIMC: qkv_w     = (const float*)d_in[i]; break;
            case DIMC * DIMC:     proj_w    = (const float*)d_in[i]; break;
            case NTOK * NTOK:     rel_idx   = (const int*)d_in[i];   break;
            case 732 * NH:        rpb_table = (const float*)d_in[i]; break;
            case DIMC:            if (nbias < 3) bias768[nbias++] = (const float*)d_in[i]; break;
            default: break;
        }
    }
    const float* q_bias = bias768[0];
    const float* v_bias = bias768[1];
    const float* proj_b = bias768[2];
    float* out = (float*)d_out;

    cudaFuncSetAttribute(attn_fused_k, cudaFuncAttributeMaxDynamicSharedMemorySize, ATT_SMEM);
    cudaFuncSetAttribute(gemm_tc<0>, cudaFuncAttributeMaxDynamicSharedMemorySize, GEMM_SMEM);
    cudaFuncSetAttribute(gemm_tc<3>, cudaFuncAttributeMaxDynamicSharedMemorySize, GEMM_SMEM);

    // 0) prepass: tf32-round operands; expand rpb
    cvt_k<<<(MROWS * DIMC / 4 + 255) / 256, 256>>>(x, MROWS * DIMC / 4, 0);
    cvt_k<<<(3 * DIMC * DIMC / 4 + 255) / 256, 256>>>(qkv_w, 3 * DIMC * DIMC / 4, 1);
    cvt_k<<<(DIMC * DIMC / 4 + 255) / 256, 256>>>(proj_w, DIMC * DIMC / 4, 2);
    rpb_expand_k<<<(NTOK * NTOK + 255) / 256, 256>>>(rel_idx, rpb_table);

    // 1) QKV projection: grid (2304/128, 25216/128)
    gemm_tc<0><<<dim3(18, 197), 128, GEMM_SMEM>>>(q_bias, v_bias, nullptr);

    // 2) fused attention
    attn_fused_k<<<NBH, 256, ATT_SMEM>>>();

    // 3) final projection + bias: grid (768/128, 197)
    gemm_tc<3><<<dim3(6, 197), 128, GEMM_SMEM>>>(proj_b, nullptr, out);
}

// round 12
// speedup vs baseline: 1.2212x; 1.0375x over previous
#include <cuda_runtime.h>
#include <cstdint>

// ---------------- problem constants ----------------
constexpr int NTOK  = 197;
constexpr int DIMC  = 768;
constexpr int NH    = 12;
constexpr int HDIM  = 64;
constexpr int NB    = 128;
constexpr int MROWS = NB * NTOK;    // 25216
constexpr int NBH   = NB * NH;      // 1536

// ---------------- scratch (device globals) ----------------
__device__ float g_q[(size_t)NBH * NTOK * HDIM];
__device__ float g_k[(size_t)NBH * NTOK * HDIM];
__device__ float g_v[(size_t)NBH * NTOK * HDIM];
__device__ float g_o[(size_t)MROWS * DIMC];      // written TF32-rounded by attention
__device__ float g_rpb[NH * NTOK * NTOK];
__device__ float g_xc[(size_t)MROWS * DIMC];     // tf32-rounded x
__device__ float g_wc[(size_t)3 * DIMC * DIMC];  // tf32-rounded qkv_w
__device__ float g_pwc[(size_t)DIMC * DIMC];     // tf32-rounded proj_w

// ---------------- helpers ----------------
__device__ __forceinline__ float f2tf32(float x) {
    unsigned u;
    asm("cvt.rna.tf32.f32 %0, %1;" : "=r"(u) : "f"(x));
    return __uint_as_float(u);
}

__device__ __forceinline__ void mma_tf32(float c[4], const float a[4], const float b[2]) {
    asm volatile(
        "mma.sync.aligned.m16n8k8.row.col.f32.tf32.tf32.f32 "
        "{%0,%1,%2,%3}, {%4,%5,%6,%7}, {%8,%9}, {%0,%1,%2,%3};"
        : "+f"(c[0]), "+f"(c[1]), "+f"(c[2]), "+f"(c[3])
        : "r"(__float_as_uint(a[0])), "r"(__float_as_uint(a[1])),
          "r"(__float_as_uint(a[2])), "r"(__float_as_uint(a[3])),
          "r"(__float_as_uint(b[0])), "r"(__float_as_uint(b[1])));
}

__device__ __forceinline__ void ldsm_x4(uint32_t addr, float d[4]) {
    uint32_t r0, r1, r2, r3;
    asm volatile("ldmatrix.sync.aligned.m8n8.x4.shared.b16 {%0,%1,%2,%3}, [%4];"
                 : "=r"(r0), "=r"(r1), "=r"(r2), "=r"(r3) : "r"(addr));
    d[0] = __uint_as_float(r0); d[1] = __uint_as_float(r1);
    d[2] = __uint_as_float(r2); d[3] = __uint_as_float(r3);
}

__device__ __forceinline__ uint32_t smem_u32(const void* p) {
    return (uint32_t)__cvta_generic_to_shared(p);
}

__device__ __forceinline__ void cp_async16(uint32_t dst, const void* src) {
    asm volatile("cp.async.cg.shared.global [%0], [%1], 16;"
                 :: "r"(dst), "l"(src) : "memory");
}
__device__ __forceinline__ void cp_commit() {
    asm volatile("cp.async.commit_group;" ::: "memory");
}
__device__ __forceinline__ void cp_wait1() {
    asm volatile("cp.async.wait_group 1;" ::: "memory");
}

// ---------------- prepass: tf32-round all operands (one kernel) -------------
constexpr int CVT_N0 = MROWS * DIMC / 4;          // x       -> g_xc
constexpr int CVT_N1 = 3 * DIMC * DIMC / 4;       // qkv_w   -> g_wc
constexpr int CVT_N2 = DIMC * DIMC / 4;           // proj_w  -> g_pwc
__global__ void cvt_all_k(const float* __restrict__ x,
                          const float* __restrict__ qw,
                          const float* __restrict__ pw)
{
    int i = blockIdx.x * 256 + threadIdx.x;
    const float4* s; float4* d;
    if (i < CVT_N0)                       { s = (const float4*)x  + i;            d = (float4*)g_xc  + i; }
    else if ((i -= CVT_N0) < CVT_N1)      { s = (const float4*)qw + i;            d = (float4*)g_wc  + i; }
    else if ((i -= CVT_N1) < CVT_N2)      { s = (const float4*)pw + i;            d = (float4*)g_pwc + i; }
    else return;
    float4 v = *s;
    *d = make_float4(f2tf32(v.x), f2tf32(v.y), f2tf32(v.z), f2tf32(v.w));
}

// ---------------- rpb gather expansion ----------------
__global__ void rpb_expand_k(const int* __restrict__ rel_idx,
                             const float* __restrict__ table)
{
    int ij = blockIdx.x * 256 + threadIdx.x;
    if (ij >= NTOK * NTOK) return;
    int rel = rel_idx[ij];
    #pragma unroll
    for (int h = 0; h < NH; h++)
        g_rpb[h * NTOK * NTOK + ij] = table[rel * NH + h];
}

// ---------------- TF32 GEMM: 128x128 block, cp.async 3-stage pipeline --------
constexpr int GBM = 128, GBN = 128, GBK = 16, GLD = 20, NSTG = 3;
constexpr int GEMM_SMEM = NSTG * (GBM + GBN) * GLD * 4;   // 61440 B

template<int MODE>
__global__ void __launch_bounds__(128, 2) gemm_tc(const float* __restrict__ P1,
                                                  const float* __restrict__ P2,
                                                  float* __restrict__ C_)
{
    constexpr int Kdim = DIMC;
    constexpr int NKT  = Kdim / GBK;               // 48

    const float* A  = (MODE == 3) ? (const float*)g_o : (const float*)g_xc;
    const float* Bm = (MODE == 3) ? (const float*)g_pwc : (const float*)g_wc;

    const int m0  = blockIdx.y * GBM;
    const int n0  = blockIdx.x * GBN;
    const int tid = threadIdx.x;
    const int w    = tid >> 5, lane = tid & 31;
    const int gid  = lane >> 2, tig = lane & 3;
    const int wm   = (w & 1) * 64;
    const int wn   = (w >> 1) * 64;

    extern __shared__ float smg[];
    float* As = smg;
    float* Bs = smg + NSTG * GBM * GLD;

    const int sr = tid >> 2;
    const int sc = (tid & 3) * 4;

    const float* pa = &A [(size_t)(m0 + sr) * Kdim + sc];
    const float* pb = &Bm[(size_t)(n0 + sr) * Kdim + sc];

    float acc[4][8][4] = {};

    const int lt   = lane >> 3;
    const int li   = lane & 7;
    const int a_row = wm + (lt & 1) * 8 + li;
    const int a_col = (lt >> 1) * 4;
    const int b_row = wn + (lt >> 1) * 8 + li;
    const int b_col = (lt & 1) * 4;

    auto STAGE = [&](int kt_idx, int buf) {
        float* ab = As + buf * GBM * GLD;
        float* bb = Bs + buf * GBN * GLD;
        const int kt = kt_idx * GBK;
        #pragma unroll
        for (int r = 0; r < 4; r++) {
            cp_async16(smem_u32(&ab[(sr + r * 32) * GLD + sc]),
                       pa + (size_t)(r * 32) * Kdim + kt);
            cp_async16(smem_u32(&bb[(sr + r * 32) * GLD + sc]),
                       pb + (size_t)(r * 32) * Kdim + kt);
        }
    };
    auto MMA_ALL = [&](int buf) {
        const float* ab = As + buf * GBM * GLD;
        const float* bb = Bs + buf * GBN * GLD;
        #pragma unroll
        for (int kc = 0; kc < 2; kc++) {
            float af[4][4], bf[8][2];
            #pragma unroll
            for (int mt = 0; mt < 4; mt++) {
                uint32_t ad = smem_u32(&ab[(a_row + mt * 16) * GLD + a_col + kc * 8]);
                ldsm_x4(ad, af[mt]);
            }
            #pragma unroll
            for (int p = 0; p < 4; p++) {
                float t4[4];
                uint32_t ad = smem_u32(&bb[(b_row + p * 16) * GLD + b_col + kc * 8]);
                ldsm_x4(ad, t4);
                bf[p*2  ][0] = t4[0]; bf[p*2  ][1] = t4[1];
                bf[p*2+1][0] = t4[2]; bf[p*2+1][1] = t4[3];
            }
            #pragma unroll
            for (int mt = 0; mt < 4; mt++)
                #pragma unroll
                for (int nt = 0; nt < 8; nt++)
                    mma_tf32(acc[mt][nt], af[mt], bf[nt]);
        }
    };

    STAGE(0, 0); cp_commit();
    STAGE(1, 1); cp_commit();
    for (int it = 0; it < NKT; it++) {
        cp_wait1();
        __syncthreads();
        if (it + 2 < NKT) STAGE(it + 2, (it + 2) % NSTG);
        cp_commit();
        MMA_ALL(it % NSTG);
    }

    #pragma unroll
    for (int mt = 0; mt < 4; mt++) {
        #pragma unroll
        for (int nt = 0; nt < 8; nt++) {
            #pragma unroll
            for (int e = 0; e < 4; e++) {
                int gm = m0 + wm + mt * 16 + gid + ((e >> 1) ? 8 : 0);
                int gn = n0 + wn + nt * 8 + tig * 2 + (e & 1);
                float v = acc[mt][nt][e];
                if (MODE == 0) {
                    int b = gm / NTOK, n = gm % NTOK;
                    int s = gn / DIMC, r = gn % DIMC;
                    int h = r / HDIM,  d = r % HDIM;
                    size_t o = ((size_t)(b * NH + h) * NTOK + n) * HDIM + d;
                    if (s == 0)      g_q[o] = (v + P1[r]) * 0.125f;
                    else if (s == 1) g_k[o] = v;
                    else             g_v[o] = v + P2[r];
                } else {
                    C_[(size_t)gm * DIMC + gn] = v + P1[gn];
                }
            }
        }
    }
}

// ---------------- fused attention: 2 CTAs per (b,h), 4 warps each ------------
// CTA pair member `half` handles row-tiles t = half, half+2, ..., (interleaved).
// smem 110.8KB/CTA, ~21.8K regs/CTA -> 2 CTAs/SM (smem-limited).
constexpr int NP        = 208;
constexpr int KS_STRIDE = 68;
constexpr int VT_STRIDE = 212;
constexpr int ATT_SMEM  = (NP * KS_STRIDE + HDIM * VT_STRIDE) * 4;

__global__ void __launch_bounds__(128, 2) attn_fused_k()
{
    const int z    = blockIdx.x >> 1;      // (b,h) index
    const int half = blockIdx.x & 1;       // which member of the pair
    const int h = z % NH;
    const int b = z / NH;
    const float* q   = g_q + (size_t)z * NTOK * HDIM;
    const float* kk  = g_k + (size_t)z * NTOK * HDIM;
    const float* vv  = g_v + (size_t)z * NTOK * HDIM;
    const float* rpb = g_rpb + (size_t)h * NTOK * NTOK;

    extern __shared__ float sm[];
    float* ks = sm;
    float* vT = sm + NP * KS_STRIDE;

    const int tid = threadIdx.x;

    for (int idx = tid; idx < NP * 16; idx += 128) {
        int tok = idx >> 4, d4 = (idx & 15) * 4;
        float4 val = make_float4(0.f, 0.f, 0.f, 0.f);
        if (tok < NTOK) val = *(const float4*)&kk[tok * HDIM + d4];
        ks[tok * KS_STRIDE + d4 + 0] = f2tf32(val.x);
        ks[tok * KS_STRIDE + d4 + 1] = f2tf32(val.y);
        ks[tok * KS_STRIDE + d4 + 2] = f2tf32(val.z);
        ks[tok * KS_STRIDE + d4 + 3] = f2tf32(val.w);
    }
    for (int idx = tid; idx < NP * 16; idx += 128) {
        int tok = idx >> 4, d4 = (idx & 15) * 4;
        float4 val = make_float4(0.f, 0.f, 0.f, 0.f);
        if (tok < NTOK) val = *(const float4*)&vv[tok * HDIM + d4];
        vT[(d4 + 0) * VT_STRIDE + tok] = f2tf32(val.x);
        vT[(d4 + 1) * VT_STRIDE + tok] = f2tf32(val.y);
        vT[(d4 + 2) * VT_STRIDE + tok] = f2tf32(val.z);
        vT[(d4 + 3) * VT_STRIDE + tok] = f2tf32(val.w);
    }
    __syncthreads();

    const int w = tid >> 5, lane = tid & 31, gid = lane >> 2, tig = lane & 3;
    const int lt = lane >> 3, li = lane & 7;
    const int bs_row = (lt >> 1) * 8 + li;
    const int bs_col = (lt & 1) * 4;

    for (int r = 0; r < 2; r++) {
        const int t = half + 2 * (w + 4 * r);   // interleaved tiles
        if (t >= 13) break;
        const int m0 = t * 16;
        const int mA = m0 + gid;
        const int mB = m0 + gid + 8;

        float aq[8][4];
        #pragma unroll
        for (int kt = 0; kt < 8; kt++) {
            int c0 = kt * 8 + tig, c1 = c0 + 4;
            aq[kt][0] = (mA < NTOK) ? f2tf32(q[mA * HDIM + c0]) : 0.f;
            aq[kt][1] = (mB < NTOK) ? f2tf32(q[mB * HDIM + c0]) : 0.f;
            aq[kt][2] = (mA < NTOK) ? f2tf32(q[mA * HDIM + c1]) : 0.f;
            aq[kt][3] = (mB < NTOK) ? f2tf32(q[mB * HDIM + c1]) : 0.f;
        }

        float acc[26][4];
        #pragma unroll
        for (int nt = 0; nt < 26; nt++)
            acc[nt][0] = acc[nt][1] = acc[nt][2] = acc[nt][3] = 0.f;
        #pragma unroll
        for (int np = 0; np < 13; np++) {
            #pragma unroll
            for (int kt = 0; kt < 8; kt++) {
                float t4[4];
                uint32_t ad = smem_u32(&ks[(np * 16 + bs_row) * KS_STRIDE + bs_col + kt * 8]);
                ldsm_x4(ad, t4);
                float bk0[2] = { t4[0], t4[1] };
                float bk1[2] = { t4[2], t4[3] };
                mma_tf32(acc[np * 2    ], aq[kt], bk0);
                mma_tf32(acc[np * 2 + 1], aq[kt], bk1);
            }
        }

        const float* rA = rpb + (size_t)min(mA, NTOK - 1) * NTOK;
        const float* rB = rpb + (size_t)min(mB, NTOK - 1) * NTOK;
        float mx0 = -1e30f, mx1 = -1e30f;
        #pragma unroll
        for (int nt = 0; nt < 26; nt++) {
            int c0 = nt * 8 + tig * 2, c1 = c0 + 1;
            acc[nt][0] = (c0 < NTOK) ? acc[nt][0] + rA[c0] : -1e30f;
            acc[nt][1] = (c1 < NTOK) ? acc[nt][1] + rA[c1] : -1e30f;
            acc[nt][2] = (c0 < NTOK) ? acc[nt][2] + rB[c0] : -1e30f;
            acc[nt][3] = (c1 < NTOK) ? acc[nt][3] + rB[c1] : -1e30f;
            mx0 = fmaxf(mx0, fmaxf(acc[nt][0], acc[nt][1]));
            mx1 = fmaxf(mx1, fmaxf(acc[nt][2], acc[nt][3]));
        }
        #pragma unroll
        for (int o = 1; o <= 2; o <<= 1) {
            mx0 = fmaxf(mx0, __shfl_xor_sync(~0u, mx0, o));
            mx1 = fmaxf(mx1, __shfl_xor_sync(~0u, mx1, o));
        }
        float s0 = 0.f, s1 = 0.f;
        #pragma unroll
        for (int nt = 0; nt < 26; nt++) {
            acc[nt][0] = __expf(acc[nt][0] - mx0);
            acc[nt][1] = __expf(acc[nt][1] - mx0);
            acc[nt][2] = __expf(acc[nt][2] - mx1);
            acc[nt][3] = __expf(acc[nt][3] - mx1);
            s0 += acc[nt][0] + acc[nt][1];
            s1 += acc[nt][2] + acc[nt][3];
        }
        #pragma unroll
        for (int o = 1; o <= 2; o <<= 1) {
            s0 += __shfl_xor_sync(~0u, s0, o);
            s1 += __shfl_xor_sync(~0u, s1, o);
        }
        const float i0 = 1.f / s0, i1 = 1.f / s1;
        #pragma unroll
        for (int nt = 0; nt < 26; nt++) {
            acc[nt][0] *= i0; acc[nt][1] *= i0;
            acc[nt][2] *= i1; acc[nt][3] *= i1;
        }

        float acc2[8][4];
        #pragma unroll
        for (int nt = 0; nt < 8; nt++)
            acc2[nt][0] = acc2[nt][1] = acc2[nt][2] = acc2[nt][3] = 0.f;

        const int src0 = (lane & ~3) | (tig >> 1);
        const int src1 = src0 + 2;
        const bool odd = tig & 1;
        #pragma unroll
        for (int kt = 0; kt < 26; kt++) {
            float v00 = __shfl_sync(~0u, acc[kt][0], src0);
            float v01 = __shfl_sync(~0u, acc[kt][1], src0);
            float v02 = __shfl_sync(~0u, acc[kt][2], src0);
            float v03 = __shfl_sync(~0u, acc[kt][3], src0);
            float w00 = __shfl_sync(~0u, acc[kt][0], src1);
            float w01 = __shfl_sync(~0u, acc[kt][1], src1);
            float w02 = __shfl_sync(~0u, acc[kt][2], src1);
            float w03 = __shfl_sync(~0u, acc[kt][3], src1);
            float aP[4];
            aP[0] = f2tf32(odd ? v01 : v00);
            aP[1] = f2tf32(odd ? v03 : v02);
            aP[2] = f2tf32(odd ? w01 : w00);
            aP[3] = f2tf32(odd ? w03 : w02);
            #pragma unroll
            for (int np = 0; np < 4; np++) {
                float t4[4];
                uint32_t ad = smem_u32(&vT[(np * 16 + bs_row) * VT_STRIDE + bs_col + kt * 8]);
                ldsm_x4(ad, t4);
                float bv0[2] = { t4[0], t4[1] };
                float bv1[2] = { t4[2], t4[3] };
                mma_tf32(acc2[np * 2    ], aP, bv0);
                mma_tf32(acc2[np * 2 + 1], aP, bv1);
            }
        }

        #pragma unroll
        for (int nt = 0; nt < 8; nt++) {
            int d0 = nt * 8 + tig * 2;
            if (mA < NTOK) {
                float* o = &g_o[((size_t)(b * NTOK + mA)) * DIMC + h * HDIM + d0];
                o[0] = f2tf32(acc2[nt][0]); o[1] = f2tf32(acc2[nt][1]);
            }
            if (mB < NTOK) {
                float* o = &g_o[((size_t)(b * NTOK + mB)) * DIMC + h * HDIM + d0];
                o[0] = f2tf32(acc2[nt][2]); o[1] = f2tf32(acc2[nt][3]);
            }
        }
    }
}

// ---------------- launch ----------------
extern "C" void kernel_launch(void* const* d_in, const int* in_sizes, int n_in,
                              void* d_out, int out_size)
{
    const float* x = nullptr; const float* qkv_w = nullptr;
    const float* proj_w = nullptr; const float* rpb_table = nullptr;
    const int*   rel_idx = nullptr;
    const float* bias768[3] = {nullptr, nullptr, nullptr};
    int nbias = 0;
    for (int i = 0; i < n_in; i++) {
        switch (in_sizes[i]) {
            case MROWS * DIMC:    x         = (const float*)d_in[i]; break;
            case 3 * DIMC * DIMC: qkv_w     = (const float*)d_in[i]; break;
            case DIMC * DIMC:     proj_w    = (const float*)d_in[i]; break;
            case NTOK * NTOK:     rel_idx   = (const int*)d_in[i];   break;
            case 732 * NH:        rpb_table = (const float*)d_in[i]; break;
            case DIMC:            if (nbias < 3) bias768[nbias++] = (const float*)d_in[i]; break;
            default: break;
        }
    }
    const float* q_bias = bias768[0];
    const float* v_bias = bias768[1];
    const float* proj_b = bias768[2];
    float* out = (float*)d_out;

    cudaFuncSetAttribute(attn_fused_k, cudaFuncAttributeMaxDynamicSharedMemorySize, ATT_SMEM);
    cudaFuncSetAttribute(gemm_tc<0>, cudaFuncAttributeMaxDynamicSharedMemorySize, GEMM_SMEM);
    cudaFuncSetAttribute(gemm_tc<3>, cudaFuncAttributeMaxDynamicSharedMemorySize, GEMM_SMEM);

    // 0) prepass: tf32-round operands (single kernel); expand rpb
    constexpr int CVT_TOT = CVT_N0 + CVT_N1 + CVT_N2;
    cvt_all_k<<<(CVT_TOT + 255) / 256, 256>>>(x, qkv_w, proj_w);
    rpb_expand_k<<<(NTOK * NTOK + 255) / 256, 256>>>(rel_idx, rpb_table);

    // 1) QKV projection: grid (2304/128, 25216/128)
    gemm_tc<0><<<dim3(18, 197), 128, GEMM_SMEM>>>(q_bias, v_bias, nullptr);

    // 2) fused attention: 2 CTAs per (b,h)
    attn_fused_k<<<NBH * 2, 128, ATT_SMEM>>>();

    // 3) final projection + bias: grid (768/128, 197)
    gemm_tc<3><<<dim3(6, 197), 128, GEMM_SMEM>>>(proj_b, nullptr, out);
}